// round 4
// baseline (speedup 1.0000x reference)
#include <cuda_runtime.h>

#define TPB    256
#define MT     64          // points per CTA
#define HDIM   256
#define DIN    16
#define DOUT   128
#define PITCH  260         // sbuf pitch: A-frag loads conflict-free ((4g+tg)%32 distinct)
#define ZPITCH 20
#define WPITCH 264         // weight-chunk pitch: B-frag loads conflict-free ((8tg+g)%32 distinct)
#define WPITCH3 136        // layer-3 weight chunk pitch (128 cols + 8)
#define WS     (16*WPITCH) // floats per weight buffer slot (4224)
#define BMAX   4096
#define NMAX   1100000

// ---------------- device scratch (no allocations allowed) ----------------
__device__ long long d_offs[BMAX + 1];
__device__ int       d_seg[NMAX];
__device__ float     d_sums[BMAX * DOUT];
__device__ float     d_emb[BMAX * DOUT];
__device__ float     d_W1t[DIN * HDIM];
__device__ float     d_W2t[HDIM * HDIM];
__device__ float     d_W3t[HDIM * DOUT];

// ---------------- helpers ----------------
__device__ __forceinline__ float to_tf32(float x) {
    float r; asm("cvt.rna.tf32.f32 %0, %1;" : "=f"(r) : "f"(x)); return r;
}

__device__ __forceinline__ void mma_tf32(float4& d,
                                         unsigned a0, unsigned a1, unsigned a2, unsigned a3,
                                         unsigned b0, unsigned b1) {
    asm volatile(
        "mma.sync.aligned.m16n8k8.row.col.f32.tf32.tf32.f32 "
        "{%0,%1,%2,%3}, {%4,%5,%6,%7}, {%8,%9}, {%0,%1,%2,%3};"
        : "+f"(d.x), "+f"(d.y), "+f"(d.z), "+f"(d.w)
        : "r"(a0), "r"(a1), "r"(a2), "r"(a3), "r"(b0), "r"(b1));
}

__device__ __forceinline__ void cp_async16(float* smem_dst, const float* gmem_src) {
    unsigned s = (unsigned)__cvta_generic_to_shared(smem_dst);
    asm volatile("cp.async.ca.shared.global [%0], [%1], 16;" :: "r"(s), "l"(gmem_src));
}
#define CP_COMMIT()  asm volatile("cp.async.commit_group;" ::: "memory")
#define CP_WAIT0()   asm volatile("cp.async.wait_group 0;" ::: "memory")

// stage a 16-row x 256-col fp32 chunk into smem at pitch WPITCH (all 256 threads)
__device__ __forceinline__ void stage_w256(float* dst, const float* src) {
    const int t = threadIdx.x;
    #pragma unroll
    for (int i = 0; i < 4; i++) {
        int idx = t + 256 * i;            // 0..1023 (16 rows x 64 float4)
        int row = idx >> 6, c4 = idx & 63;
        cp_async16(dst + row * WPITCH + 4 * c4, src + row * 256 + 4 * c4);
    }
}
// stage a 16-row x 128-col chunk at pitch WPITCH3
__device__ __forceinline__ void stage_w128(float* dst, const float* src) {
    const int t = threadIdx.x;
    #pragma unroll
    for (int i = 0; i < 2; i++) {
        int idx = t + 256 * i;            // 0..511 (16 rows x 32 float4)
        int row = idx >> 5, c4 = idx & 31;
        cp_async16(dst + row * WPITCH3 + 4 * c4, src + row * 128 + 4 * c4);
    }
}

__device__ __forceinline__ long long get_count(const void* np, int i, int is64) {
    if (is64) return ((const long long*)np)[i];
    return (long long)((const int*)np)[i];
}

// ---------------- small setup kernels ----------------
__global__ void scan_offsets(const void* __restrict__ np, int Bn) {
    __shared__ long long part[256];
    __shared__ int s_is64;
    if (threadIdx.x == 0) {
        const int* p32 = (const int*)np;
        int is64 = 1;
        for (int i = 1; i < 7 && i < 2 * Bn; i += 2)
            if (p32[i] != 0) is64 = 0;
        s_is64 = is64;
    }
    __syncthreads();
    const int is64 = s_is64;
    const int chunk = (Bn + 255) / 256;
    const int c0 = threadIdx.x * chunk;
    long long s = 0;
    for (int i = 0; i < chunk; i++) {
        int idx = c0 + i;
        if (idx < Bn) s += get_count(np, idx, is64);
    }
    part[threadIdx.x] = s;
    __syncthreads();
    if (threadIdx.x == 0) {
        long long r = 0;
        for (int i = 0; i < 256; i++) { long long t = part[i]; part[i] = r; r += t; }
    }
    __syncthreads();
    long long base = part[threadIdx.x];
    for (int i = 0; i < chunk; i++) {
        int idx = c0 + i;
        if (idx < Bn) {
            d_offs[idx] = base;
            base += get_count(np, idx, is64);
            if (idx == Bn - 1) d_offs[Bn] = base;
        }
    }
}

__global__ void fill_seg(int Bn) {
    int b = blockIdx.x;
    long long lo = d_offs[b], hi = d_offs[b + 1];
    for (long long i = lo + threadIdx.x; i < hi; i += blockDim.x)
        d_seg[i] = b;
}

__global__ void zero_sums(int n) {
    int i = blockIdx.x * blockDim.x + threadIdx.x;
    if (i < n) d_sums[i] = 0.f;
}

__global__ void cvt_weights(const float* __restrict__ W1,
                            const float* __restrict__ W2,
                            const float* __restrict__ W3) {
    int i = blockIdx.x * 256 + threadIdx.x;
    if (i < DIN * HDIM)  d_W1t[i] = to_tf32(W1[i]);
    if (i < HDIM * HDIM) d_W2t[i] = to_tf32(W2[i]);
    if (i < HDIM * DOUT) d_W3t[i] = to_tf32(W3[i]);
}

// ---------------- LN + ReLU over sbuf [64][PITCH] ----------------
__device__ __forceinline__ void ln_relu(float* sbuf, const float* bi, const float* ga,
                                        const float* be, int tid) {
    const int p = tid >> 2, l = tid & 3;
    float* row = sbuf + p * PITCH;
    float s = 0.f, q = 0.f;
    #pragma unroll
    for (int i = 0; i < 16; i++) {
        int c = 4 * (l + 4 * i);
        float4 x = *(const float4*)(row + c);
        float4 bb = *(const float4*)(bi + c);
        x.x += bb.x; x.y += bb.y; x.z += bb.z; x.w += bb.w;
        s += x.x + x.y + x.z + x.w;
        q += x.x * x.x + x.y * x.y + x.z * x.z + x.w * x.w;
    }
    s += __shfl_xor_sync(0xffffffffu, s, 1);
    q += __shfl_xor_sync(0xffffffffu, q, 1);
    s += __shfl_xor_sync(0xffffffffu, s, 2);
    q += __shfl_xor_sync(0xffffffffu, q, 2);
    const float m = s * (1.f / 256.f);
    const float r = rsqrtf(q * (1.f / 256.f) - m * m + 1e-5f);
    #pragma unroll
    for (int i = 0; i < 16; i++) {
        int c = 4 * (l + 4 * i);
        float4 x  = *(const float4*)(row + c);
        float4 bb = *(const float4*)(bi + c);
        float4 gg = *(const float4*)(ga + c);
        float4 ee = *(const float4*)(be + c);
        float4 y;
        y.x = to_tf32(fmaxf((x.x + bb.x - m) * r * gg.x + ee.x, 0.f));
        y.y = to_tf32(fmaxf((x.y + bb.y - m) * r * gg.y + ee.y, 0.f));
        y.z = to_tf32(fmaxf((x.z + bb.z - m) * r * gg.z + ee.z, 0.f));
        y.w = to_tf32(fmaxf((x.w + bb.w - m) * r * gg.w + ee.w, 0.f));
        *(float4*)(row + c) = y;
    }
}

// ---------------- main fused kernel ----------------
__global__ __launch_bounds__(TPB, 2)
void mlp_mma(const float* __restrict__ z,
             const float* __restrict__ b1, const float* __restrict__ g1, const float* __restrict__ be1,
             const float* __restrict__ b2, const float* __restrict__ g2, const float* __restrict__ be2,
             const float* __restrict__ b3,
             int Npts)
{
    extern __shared__ char smem_raw[];
    float* sbuf = (float*)smem_raw;                 // 64*PITCH
    float* zs   = sbuf + MT * PITCH;                // 64*ZPITCH
    float* sb1  = zs + MT * ZPITCH;
    float* sg1  = sb1 + HDIM;
    float* sbe1 = sg1 + HDIM;
    float* sb2  = sbe1 + HDIM;
    float* sg2  = sb2 + HDIM;
    float* sbe2 = sg2 + HDIM;
    float* sb3  = sbe2 + HDIM;                      // 128
    int*   ssg  = (int*)(sb3 + DOUT);               // 64 ints
    float* wbuf = (float*)(ssg + MT);               // 2 * WS floats

    const int tid = threadIdx.x;
    const int p0 = blockIdx.x * MT;
    const int npts = min(MT, Npts - p0);
    if (npts <= 0) return;

    // ---- prologue: async-stage W1 into wbuf slot0, then load z/params ----
    stage_w256(wbuf, d_W1t);     // W1 is exactly 16x256
    CP_COMMIT();

    {
        const float4* z4 = (const float4*)(z + (long long)p0 * DIN);
        int pi = tid >> 2, ci = tid & 3;
        float4 v = make_float4(0.f, 0.f, 0.f, 0.f);
        if (pi < npts) v = z4[pi * 4 + ci];
        float* zr = zs + pi * ZPITCH + 4 * ci;
        zr[0] = to_tf32(v.x); zr[1] = to_tf32(v.y); zr[2] = to_tf32(v.z); zr[3] = to_tf32(v.w);

        sb1[tid] = b1[tid]; sg1[tid] = g1[tid]; sbe1[tid] = be1[tid];
        sb2[tid] = b2[tid]; sg2[tid] = g2[tid]; sbe2[tid] = be2[tid];
        if (tid < DOUT) sb3[tid] = b3[tid];
        if (tid < MT) ssg[tid] = (tid < npts) ? d_seg[p0 + tid] : 0;
    }
    CP_WAIT0();
    __syncthreads();

    const int warp = tid >> 5, lane = tid & 31;
    const int g = lane >> 2, tg = lane & 3;
    const int n0 = warp * 32;

    // ================= Layer 1: [64x16] @ [16x256], W1 from smem =================
    {
        float4 acc[4][4];
        #pragma unroll
        for (int m = 0; m < 4; m++)
            #pragma unroll
            for (int t = 0; t < 4; t++) acc[m][t] = make_float4(0.f, 0.f, 0.f, 0.f);

        #pragma unroll
        for (int ks = 0; ks < 2; ks++) {
            const int k = 8 * ks;
            unsigned a[4][4];
            #pragma unroll
            for (int m = 0; m < 4; m++) {
                const float* ar = zs + (16 * m + g) * ZPITCH + k + tg;
                a[m][0] = __float_as_uint(ar[0]);
                a[m][1] = __float_as_uint(ar[8 * ZPITCH]);
                a[m][2] = __float_as_uint(ar[4]);
                a[m][3] = __float_as_uint(ar[8 * ZPITCH + 4]);
            }
            #pragma unroll
            for (int t = 0; t < 4; t++) {
                const int n = n0 + 8 * t;
                unsigned w0 = __float_as_uint(wbuf[(k + tg) * WPITCH + n + g]);
                unsigned w1 = __float_as_uint(wbuf[(k + tg + 4) * WPITCH + n + g]);
                #pragma unroll
                for (int m = 0; m < 4; m++)
                    mma_tf32(acc[m][t], a[m][0], a[m][1], a[m][2], a[m][3], w0, w1);
            }
        }
        #pragma unroll
        for (int m = 0; m < 4; m++)
            #pragma unroll
            for (int t = 0; t < 4; t++) {
                float* cr = sbuf + (16 * m + g) * PITCH + n0 + 8 * t + 2 * tg;
                cr[0] = acc[m][t].x; cr[1] = acc[m][t].y;
                cr[8 * PITCH] = acc[m][t].z; cr[8 * PITCH + 1] = acc[m][t].w;
            }
    }
    // prefetch layer-2 chunk 0 into slot1 (slot1 unused; slot0 readers done after next sync)
    stage_w256(wbuf + WS, d_W2t);
    CP_COMMIT();
    __syncthreads();
    ln_relu(sbuf, sb1, sg1, sbe1, tid);
    __syncthreads();

    // ================= Layer 2: [64x256] @ [256x256], cp.async double-buffered =================
    {
        float4 acc[4][4];
        #pragma unroll
        for (int m = 0; m < 4; m++)
            #pragma unroll
            for (int t = 0; t < 4; t++) acc[m][t] = make_float4(0.f, 0.f, 0.f, 0.f);

        for (int c = 0; c < 16; c++) {
            CP_WAIT0();
            __syncthreads();            // chunk c visible CTA-wide; compute(c-1) done CTA-wide
            if (c + 1 < 16) {
                stage_w256(wbuf + (c & 1) * WS, d_W2t + (c + 1) * 16 * 256);
                CP_COMMIT();
            }
            const float* wb = wbuf + ((c + 1) & 1) * WS;
            #pragma unroll
            for (int ks = 0; ks < 2; ks++) {
                const int k = 16 * c + 8 * ks;   // A column
                const int kp = 8 * ks;           // row within chunk
                unsigned a[4][4];
                #pragma unroll
                for (int m = 0; m < 4; m++) {
                    const float* ar = sbuf + (16 * m + g) * PITCH + k + tg;
                    a[m][0] = __float_as_uint(ar[0]);
                    a[m][1] = __float_as_uint(ar[8 * PITCH]);
                    a[m][2] = __float_as_uint(ar[4]);
                    a[m][3] = __float_as_uint(ar[8 * PITCH + 4]);
                }
                #pragma unroll
                for (int t = 0; t < 4; t++) {
                    const int n = n0 + 8 * t;
                    unsigned w0 = __float_as_uint(wb[(kp + tg) * WPITCH + n + g]);
                    unsigned w1 = __float_as_uint(wb[(kp + tg + 4) * WPITCH + n + g]);
                    #pragma unroll
                    for (int m = 0; m < 4; m++)
                        mma_tf32(acc[m][t], a[m][0], a[m][1], a[m][2], a[m][3], w0, w1);
                }
            }
        }
        __syncthreads();   // all A reads + chunk reads done before overwriting sbuf / wbuf
        // prefetch layer-3 chunk 0 into slot1 (last layer-2 chunk was in slot0)
        stage_w128(wbuf + WS, d_W3t);
        CP_COMMIT();
        #pragma unroll
        for (int m = 0; m < 4; m++)
            #pragma unroll
            for (int t = 0; t < 4; t++) {
                float* cr = sbuf + (16 * m + g) * PITCH + n0 + 8 * t + 2 * tg;
                cr[0] = acc[m][t].x; cr[1] = acc[m][t].y;
                cr[8 * PITCH] = acc[m][t].z; cr[8 * PITCH + 1] = acc[m][t].w;
            }
    }
    __syncthreads();
    ln_relu(sbuf, sb2, sg2, sbe2, tid);
    __syncthreads();

    // ================= Layer 3: [64x256] @ [256x128], cp.async double-buffered =================
    {
        const int n3 = warp * 16;
        float4 acc[4][2];
        #pragma unroll
        for (int m = 0; m < 4; m++)
            #pragma unroll
            for (int t = 0; t < 2; t++) acc[m][t] = make_float4(0.f, 0.f, 0.f, 0.f);

        for (int c = 0; c < 16; c++) {
            CP_WAIT0();
            __syncthreads();
            if (c + 1 < 16) {
                stage_w128(wbuf + (c & 1) * WS, d_W3t + (c + 1) * 16 * 128);
                CP_COMMIT();
            }
            const float* wb = wbuf + ((c + 1) & 1) * WS;
            #pragma unroll
            for (int ks = 0; ks < 2; ks++) {
                const int k = 16 * c + 8 * ks;
                const int kp = 8 * ks;
                unsigned a[4][4];
                #pragma unroll
                for (int m = 0; m < 4; m++) {
                    const float* ar = sbuf + (16 * m + g) * PITCH + k + tg;
                    a[m][0] = __float_as_uint(ar[0]);
                    a[m][1] = __float_as_uint(ar[8 * PITCH]);
                    a[m][2] = __float_as_uint(ar[4]);
                    a[m][3] = __float_as_uint(ar[8 * PITCH + 4]);
                }
                #pragma unroll
                for (int t = 0; t < 2; t++) {
                    const int n = n3 + 8 * t;
                    unsigned w0 = __float_as_uint(wb[(kp + tg) * WPITCH3 + n + g]);
                    unsigned w1 = __float_as_uint(wb[(kp + tg + 4) * WPITCH3 + n + g]);
                    #pragma unroll
                    for (int m = 0; m < 4; m++)
                        mma_tf32(acc[m][t], a[m][0], a[m][1], a[m][2], a[m][3], w0, w1);
                }
            }
        }
        __syncthreads();
        #pragma unroll
        for (int m = 0; m < 4; m++)
            #pragma unroll
            for (int t = 0; t < 2; t++) {
                float* cr = sbuf + (16 * m + g) * PITCH + n3 + 8 * t + 2 * tg;
                cr[0] = acc[m][t].x; cr[1] = acc[m][t].y;
                cr[8 * PITCH] = acc[m][t].z; cr[8 * PITCH + 1] = acc[m][t].w;
            }
    }
    __syncthreads();

    // ================= epilogue: bias + run-length segment accumulate =================
    {
        const int f = tid & (DOUT - 1);
        const int half = tid >> 7;
        const int ps = half * 32;
        const int pe = min(ps + 32, npts);
        if (ps < pe) {
            const float bf = sb3[f];
            int cur = ssg[ps];
            float run = 0.f;
            for (int p = ps; p < pe; p++) {
                float phi = sbuf[p * PITCH + f] + bf;
                int sp = ssg[p];
                if (sp != cur) {
                    atomicAdd(&d_sums[cur * DOUT + f], run);
                    run = 0.f;
                    cur = sp;
                }
                run += phi;
            }
            atomicAdd(&d_sums[cur * DOUT + f], run);
        }
    }
}

__global__ void finalize_means(int Bn) {
    int i = blockIdx.x * blockDim.x + threadIdx.x;
    if (i < Bn * DOUT) {
        int b = i >> 7;
        float cnt = (float)(d_offs[b + 1] - d_offs[b]);
        d_emb[i] = d_sums[i] / cnt;
    }
}

__global__ void broadcast_out(float4* __restrict__ out, long long total4) {
    long long i = (long long)blockIdx.x * blockDim.x + threadIdx.x;
    if (i < total4) {
        long long p = i >> 5;
        int c = (int)(i & 31);
        const float4* emb4 = reinterpret_cast<const float4*>(d_emb);
        out[i] = emb4[(long long)d_seg[p] * 32 + c];
    }
}

extern "C" void kernel_launch(void* const* d_in, const int* in_sizes, int n_in,
                              void* d_out, int out_size) {
    const float* z   = (const float*)d_in[0];
    const float* W1  = (const float*)d_in[1];
    const float* b1  = (const float*)d_in[2];
    const float* g1  = (const float*)d_in[3];
    const float* be1 = (const float*)d_in[4];
    const float* W2  = (const float*)d_in[5];
    const float* b2  = (const float*)d_in[6];
    const float* g2  = (const float*)d_in[7];
    const float* be2 = (const float*)d_in[8];
    const float* W3  = (const float*)d_in[9];
    const float* b3  = (const float*)d_in[10];
    const void*  np  = d_in[11];

    const int Bn = in_sizes[11];
    const int N  = in_sizes[0] / DIN;

    static const size_t SMEM_BYTES =
        (MT * PITCH + MT * ZPITCH + 6 * HDIM + DOUT + 2 * WS) * sizeof(float)
        + MT * sizeof(int);
    cudaFuncSetAttribute(mlp_mma, cudaFuncAttributeMaxDynamicSharedMemorySize,
                         (int)SMEM_BYTES);

    scan_offsets<<<1, 256>>>(np, Bn);
    fill_seg<<<Bn, 128>>>(Bn);
    zero_sums<<<(Bn * DOUT + 255) / 256, 256>>>(Bn * DOUT);
    cvt_weights<<<256, 256>>>(W1, W2, W3);

    const int tiles = (N + MT - 1) / MT;
    mlp_mma<<<tiles, TPB, SMEM_BYTES>>>(z, b1, g1, be1, b2, g2, be2, b3, N);

    finalize_means<<<(Bn * DOUT + 255) / 256, 256>>>(Bn);

    const long long total4 = (long long)N * (DOUT / 4);
    broadcast_out<<<(int)((total4 + 255) / 256), 256>>>((float4*)d_out, total4);
}

// round 5
// speedup vs baseline: 1.3732x; 1.3732x over previous
#include <cuda_runtime.h>

#define TPB    256
#define MT     64          // points per CTA
#define HDIM   256
#define DIN    16
#define DOUT   128
#define PITCH  260         // sbuf pitch: A-frag LDS conflict-free ((4g+tg)%32 distinct)
#define ZPITCH 20
#define BMAX   4096
#define NMAX   1100000

// ---------------- device scratch (no allocations allowed) ----------------
__device__ long long d_offs[BMAX + 1];
__device__ int       d_seg[NMAX];
__device__ float     d_sums[BMAX * DOUT];
__device__ float     d_emb[BMAX * DOUT];
// k-pair packed tf32 weights: index (koct*N + n)*4 + tg  ->  {W[8koct+tg][n], W[8koct+tg+4][n]}
__device__ float2    d_W1p[2  * HDIM * 4];
__device__ float2    d_W2p[32 * HDIM * 4];
__device__ float2    d_W3p[32 * DOUT * 4];

// ---------------- helpers ----------------
__device__ __forceinline__ float to_tf32(float x) {
    float r; asm("cvt.rna.tf32.f32 %0, %1;" : "=f"(r) : "f"(x)); return r;
}

__device__ __forceinline__ void mma_tf32(float4& d,
                                         unsigned a0, unsigned a1, unsigned a2, unsigned a3,
                                         unsigned b0, unsigned b1) {
    asm volatile(
        "mma.sync.aligned.m16n8k8.row.col.f32.tf32.tf32.f32 "
        "{%0,%1,%2,%3}, {%4,%5,%6,%7}, {%8,%9}, {%0,%1,%2,%3};"
        : "+f"(d.x), "+f"(d.y), "+f"(d.z), "+f"(d.w)
        : "r"(a0), "r"(a1), "r"(a2), "r"(a3), "r"(b0), "r"(b1));
}

__device__ __forceinline__ long long get_count(const void* np, int i, int is64) {
    if (is64) return ((const long long*)np)[i];
    return (long long)((const int*)np)[i];
}

// ---------------- small setup kernels ----------------
__global__ void scan_offsets(const void* __restrict__ np, int Bn) {
    __shared__ long long part[256];
    __shared__ int s_is64;
    if (threadIdx.x == 0) {
        const int* p32 = (const int*)np;
        int is64 = 1;
        for (int i = 1; i < 7 && i < 2 * Bn; i += 2)
            if (p32[i] != 0) is64 = 0;
        s_is64 = is64;
    }
    __syncthreads();
    const int is64 = s_is64;
    const int chunk = (Bn + 255) / 256;
    const int c0 = threadIdx.x * chunk;
    long long s = 0;
    for (int i = 0; i < chunk; i++) {
        int idx = c0 + i;
        if (idx < Bn) s += get_count(np, idx, is64);
    }
    part[threadIdx.x] = s;
    __syncthreads();
    if (threadIdx.x == 0) {
        long long r = 0;
        for (int i = 0; i < 256; i++) { long long t = part[i]; part[i] = r; r += t; }
    }
    __syncthreads();
    long long base = part[threadIdx.x];
    for (int i = 0; i < chunk; i++) {
        int idx = c0 + i;
        if (idx < Bn) {
            d_offs[idx] = base;
            base += get_count(np, idx, is64);
            if (idx == Bn - 1) d_offs[Bn] = base;
        }
    }
}

__global__ void fill_seg(int Bn) {
    int b = blockIdx.x;
    long long lo = d_offs[b], hi = d_offs[b + 1];
    for (long long i = lo + threadIdx.x; i < hi; i += blockDim.x)
        d_seg[i] = b;
}

__global__ void zero_sums(int n) {
    int i = blockIdx.x * blockDim.x + threadIdx.x;
    if (i < n) d_sums[i] = 0.f;
}

// pack + tf32-truncate weights into k-pair float2 layout
__global__ void cvt_weights(const float* __restrict__ W1,
                            const float* __restrict__ W2,
                            const float* __restrict__ W3) {
    int i = blockIdx.x * 256 + threadIdx.x;   // launched with 32768 threads
    if (i < 32 * HDIM * 4) {
        int tg = i & 3, n = (i >> 2) & (HDIM - 1), ko = i >> 10;
        d_W2p[i] = make_float2(to_tf32(W2[(8 * ko + tg) * HDIM + n]),
                               to_tf32(W2[(8 * ko + tg + 4) * HDIM + n]));
    }
    if (i < 32 * DOUT * 4) {
        int tg = i & 3, n = (i >> 2) & (DOUT - 1), ko = i >> 9;
        d_W3p[i] = make_float2(to_tf32(W3[(8 * ko + tg) * DOUT + n]),
                               to_tf32(W3[(8 * ko + tg + 4) * DOUT + n]));
    }
    if (i < 2 * HDIM * 4) {
        int tg = i & 3, n = (i >> 2) & (HDIM - 1), ko = i >> 10;
        d_W1p[i] = make_float2(to_tf32(W1[(8 * ko + tg) * HDIM + n]),
                               to_tf32(W1[(8 * ko + tg + 4) * HDIM + n]));
    }
}

// ---------------- LN + ReLU over sbuf [64][PITCH] ----------------
__device__ __forceinline__ void ln_relu(float* sbuf, const float* bi, const float* ga,
                                        const float* be, int tid) {
    const int p = tid >> 2, l = tid & 3;
    float* row = sbuf + p * PITCH;
    float s = 0.f, q = 0.f;
    #pragma unroll
    for (int i = 0; i < 16; i++) {
        int c = 4 * (l + 4 * i);
        float4 x = *(const float4*)(row + c);
        float4 bb = *(const float4*)(bi + c);
        x.x += bb.x; x.y += bb.y; x.z += bb.z; x.w += bb.w;
        s += x.x + x.y + x.z + x.w;
        q += x.x * x.x + x.y * x.y + x.z * x.z + x.w * x.w;
    }
    s += __shfl_xor_sync(0xffffffffu, s, 1);
    q += __shfl_xor_sync(0xffffffffu, q, 1);
    s += __shfl_xor_sync(0xffffffffu, s, 2);
    q += __shfl_xor_sync(0xffffffffu, q, 2);
    const float m = s * (1.f / 256.f);
    const float r = rsqrtf(q * (1.f / 256.f) - m * m + 1e-5f);
    #pragma unroll
    for (int i = 0; i < 16; i++) {
        int c = 4 * (l + 4 * i);
        float4 x  = *(const float4*)(row + c);
        float4 bb = *(const float4*)(bi + c);
        float4 gg = *(const float4*)(ga + c);
        float4 ee = *(const float4*)(be + c);
        float4 y;
        y.x = to_tf32(fmaxf((x.x + bb.x - m) * r * gg.x + ee.x, 0.f));
        y.y = to_tf32(fmaxf((x.y + bb.y - m) * r * gg.y + ee.y, 0.f));
        y.z = to_tf32(fmaxf((x.z + bb.z - m) * r * gg.z + ee.z, 0.f));
        y.w = to_tf32(fmaxf((x.w + bb.w - m) * r * gg.w + ee.w, 0.f));
        *(float4*)(row + c) = y;
    }
}

// ---------------- main fused kernel ----------------
__global__ __launch_bounds__(TPB, 2)
void mlp_mma(const float* __restrict__ z,
             const float* __restrict__ b1, const float* __restrict__ g1, const float* __restrict__ be1,
             const float* __restrict__ b2, const float* __restrict__ g2, const float* __restrict__ be2,
             const float* __restrict__ b3,
             int Npts)
{
    extern __shared__ char smem_raw[];
    float* sbuf = (float*)smem_raw;                 // 64*PITCH
    float* zs   = sbuf + MT * PITCH;                // 64*ZPITCH
    float* sb1  = zs + MT * ZPITCH;
    float* sg1  = sb1 + HDIM;
    float* sbe1 = sg1 + HDIM;
    float* sb2  = sbe1 + HDIM;
    float* sg2  = sb2 + HDIM;
    float* sbe2 = sg2 + HDIM;
    float* sb3  = sbe2 + HDIM;                      // 128
    int*   ssg  = (int*)(sb3 + DOUT);               // 64

    const int tid = threadIdx.x;
    const int p0 = blockIdx.x * MT;
    const int npts = min(MT, Npts - p0);
    if (npts <= 0) return;

    const int warp = tid >> 5, lane = tid & 31;
    const int g = lane >> 2, tg = lane & 3;
    const int n0 = warp * 32;                       // 32-col slice for H=256 layers
    const int n3 = warp * 16;                       // 16-col slice for DOUT=128

    // ---- load z tile (tf32-truncated), params, seg ids ----
    // preload W1 (both k-chunks) into regs while smem fills
    float2 w1p[2][4];
    #pragma unroll
    for (int ks = 0; ks < 2; ks++)
        #pragma unroll
        for (int t = 0; t < 4; t++)
            w1p[ks][t] = d_W1p[(ks * HDIM + n0 + 8 * t + g) * 4 + tg];

    {
        const float4* z4 = (const float4*)(z + (long long)p0 * DIN);
        int pi = tid >> 2, ci = tid & 3;
        float4 v = make_float4(0.f, 0.f, 0.f, 0.f);
        if (pi < npts) v = z4[pi * 4 + ci];
        float* zr = zs + pi * ZPITCH + 4 * ci;
        zr[0] = to_tf32(v.x); zr[1] = to_tf32(v.y); zr[2] = to_tf32(v.z); zr[3] = to_tf32(v.w);

        sb1[tid] = b1[tid]; sg1[tid] = g1[tid]; sbe1[tid] = be1[tid];
        sb2[tid] = b2[tid]; sg2[tid] = g2[tid]; sbe2[tid] = be2[tid];
        if (tid < DOUT) sb3[tid] = b3[tid];
        if (tid < MT) ssg[tid] = (tid < npts) ? d_seg[p0 + tid] : 0;
    }
    __syncthreads();

    float2 bw0[4], bw1[4];   // B-fragment pipeline registers

    // ================= Layer 1: [64x16] @ [16x256] =================
    {
        float4 acc[4][4];
        #pragma unroll
        for (int m = 0; m < 4; m++)
            #pragma unroll
            for (int t = 0; t < 4; t++) acc[m][t] = make_float4(0.f, 0.f, 0.f, 0.f);

        #pragma unroll
        for (int ks = 0; ks < 2; ks++) {
            const int k = 8 * ks;
            unsigned a[4][4];
            #pragma unroll
            for (int m = 0; m < 4; m++) {
                const float* ar = zs + (16 * m + g) * ZPITCH + k + tg;
                a[m][0] = __float_as_uint(ar[0]);
                a[m][1] = __float_as_uint(ar[8 * ZPITCH]);
                a[m][2] = __float_as_uint(ar[4]);
                a[m][3] = __float_as_uint(ar[8 * ZPITCH + 4]);
            }
            #pragma unroll
            for (int t = 0; t < 4; t++)
                #pragma unroll
                for (int m = 0; m < 4; m++)
                    mma_tf32(acc[m][t], a[m][0], a[m][1], a[m][2], a[m][3],
                             __float_as_uint(w1p[ks][t].x), __float_as_uint(w1p[ks][t].y));
        }
        #pragma unroll
        for (int m = 0; m < 4; m++)
            #pragma unroll
            for (int t = 0; t < 4; t++) {
                float* cr = sbuf + (16 * m + g) * PITCH + n0 + 8 * t + 2 * tg;
                cr[0] = acc[m][t].x; cr[1] = acc[m][t].y;
                cr[8 * PITCH] = acc[m][t].z; cr[8 * PITCH + 1] = acc[m][t].w;
            }
    }
    // preload layer-2 chunk 0 (L2 latency hidden under LN1)
    #pragma unroll
    for (int t = 0; t < 4; t++)
        bw0[t] = d_W2p[(n0 + 8 * t + g) * 4 + tg];
    __syncthreads();
    ln_relu(sbuf, sb1, sg1, sbe1, tid);
    __syncthreads();

    // ================= Layer 2: [64x256] @ [256x256], reg-pipelined =================
    {
        float4 acc[4][4];
        #pragma unroll
        for (int m = 0; m < 4; m++)
            #pragma unroll
            for (int t = 0; t < 4; t++) acc[m][t] = make_float4(0.f, 0.f, 0.f, 0.f);

        #pragma unroll 1
        for (int c = 0; c < 32; c += 2) {
            // prefetch chunk c+1
            #pragma unroll
            for (int t = 0; t < 4; t++)
                bw1[t] = d_W2p[((c + 1) * HDIM + n0 + 8 * t + g) * 4 + tg];
            // compute chunk c (bw0)
            {
                const int k = 8 * c;
                unsigned a[4][4];
                #pragma unroll
                for (int m = 0; m < 4; m++) {
                    const float* ar = sbuf + (16 * m + g) * PITCH + k + tg;
                    a[m][0] = __float_as_uint(ar[0]);
                    a[m][1] = __float_as_uint(ar[8 * PITCH]);
                    a[m][2] = __float_as_uint(ar[4]);
                    a[m][3] = __float_as_uint(ar[8 * PITCH + 4]);
                }
                #pragma unroll
                for (int t = 0; t < 4; t++)
                    #pragma unroll
                    for (int m = 0; m < 4; m++)
                        mma_tf32(acc[m][t], a[m][0], a[m][1], a[m][2], a[m][3],
                                 __float_as_uint(bw0[t].x), __float_as_uint(bw0[t].y));
            }
            // prefetch chunk c+2
            if (c + 2 < 32) {
                #pragma unroll
                for (int t = 0; t < 4; t++)
                    bw0[t] = d_W2p[((c + 2) * HDIM + n0 + 8 * t + g) * 4 + tg];
            }
            // compute chunk c+1 (bw1)
            {
                const int k = 8 * (c + 1);
                unsigned a[4][4];
                #pragma unroll
                for (int m = 0; m < 4; m++) {
                    const float* ar = sbuf + (16 * m + g) * PITCH + k + tg;
                    a[m][0] = __float_as_uint(ar[0]);
                    a[m][1] = __float_as_uint(ar[8 * PITCH]);
                    a[m][2] = __float_as_uint(ar[4]);
                    a[m][3] = __float_as_uint(ar[8 * PITCH + 4]);
                }
                #pragma unroll
                for (int t = 0; t < 4; t++)
                    #pragma unroll
                    for (int m = 0; m < 4; m++)
                        mma_tf32(acc[m][t], a[m][0], a[m][1], a[m][2], a[m][3],
                                 __float_as_uint(bw1[t].x), __float_as_uint(bw1[t].y));
            }
        }
        __syncthreads();   // all A reads done before overwriting sbuf
        #pragma unroll
        for (int m = 0; m < 4; m++)
            #pragma unroll
            for (int t = 0; t < 4; t++) {
                float* cr = sbuf + (16 * m + g) * PITCH + n0 + 8 * t + 2 * tg;
                cr[0] = acc[m][t].x; cr[1] = acc[m][t].y;
                cr[8 * PITCH] = acc[m][t].z; cr[8 * PITCH + 1] = acc[m][t].w;
            }
    }
    // preload layer-3 chunk 0 (hidden under LN2)
    #pragma unroll
    for (int t = 0; t < 2; t++)
        bw0[t] = d_W3p[(n3 + 8 * t + g) * 4 + tg];
    __syncthreads();
    ln_relu(sbuf, sb2, sg2, sbe2, tid);
    __syncthreads();

    // ================= Layer 3: [64x256] @ [256x128], reg-pipelined =================
    {
        float4 acc[4][2];
        #pragma unroll
        for (int m = 0; m < 4; m++)
            #pragma unroll
            for (int t = 0; t < 2; t++) acc[m][t] = make_float4(0.f, 0.f, 0.f, 0.f);

        #pragma unroll 1
        for (int c = 0; c < 32; c += 2) {
            #pragma unroll
            for (int t = 0; t < 2; t++)
                bw1[t] = d_W3p[((c + 1) * DOUT + n3 + 8 * t + g) * 4 + tg];
            {
                const int k = 8 * c;
                unsigned a[4][4];
                #pragma unroll
                for (int m = 0; m < 4; m++) {
                    const float* ar = sbuf + (16 * m + g) * PITCH + k + tg;
                    a[m][0] = __float_as_uint(ar[0]);
                    a[m][1] = __float_as_uint(ar[8 * PITCH]);
                    a[m][2] = __float_as_uint(ar[4]);
                    a[m][3] = __float_as_uint(ar[8 * PITCH + 4]);
                }
                #pragma unroll
                for (int t = 0; t < 2; t++)
                    #pragma unroll
                    for (int m = 0; m < 4; m++)
                        mma_tf32(acc[m][t], a[m][0], a[m][1], a[m][2], a[m][3],
                                 __float_as_uint(bw0[t].x), __float_as_uint(bw0[t].y));
            }
            if (c + 2 < 32) {
                #pragma unroll
                for (int t = 0; t < 2; t++)
                    bw0[t] = d_W3p[((c + 2) * DOUT + n3 + 8 * t + g) * 4 + tg];
            }
            {
                const int k = 8 * (c + 1);
                unsigned a[4][4];
                #pragma unroll
                for (int m = 0; m < 4; m++) {
                    const float* ar = sbuf + (16 * m + g) * PITCH + k + tg;
                    a[m][0] = __float_as_uint(ar[0]);
                    a[m][1] = __float_as_uint(ar[8 * PITCH]);
                    a[m][2] = __float_as_uint(ar[4]);
                    a[m][3] = __float_as_uint(ar[8 * PITCH + 4]);
                }
                #pragma unroll
                for (int t = 0; t < 2; t++)
                    #pragma unroll
                    for (int m = 0; m < 4; m++)
                        mma_tf32(acc[m][t], a[m][0], a[m][1], a[m][2], a[m][3],
                                 __float_as_uint(bw1[t].x), __float_as_uint(bw1[t].y));
            }
        }
        __syncthreads();
        #pragma unroll
        for (int m = 0; m < 4; m++)
            #pragma unroll
            for (int t = 0; t < 2; t++) {
                float* cr = sbuf + (16 * m + g) * PITCH + n3 + 8 * t + 2 * tg;
                cr[0] = acc[m][t].x; cr[1] = acc[m][t].y;
                cr[8 * PITCH] = acc[m][t].z; cr[8 * PITCH + 1] = acc[m][t].w;
            }
    }
    __syncthreads();

    // ================= epilogue: bias + run-length segment accumulate =================
    {
        const int f = tid & (DOUT - 1);
        const int half = tid >> 7;
        const int ps = half * 32;
        const int pe = min(ps + 32, npts);
        if (ps < pe) {
            const float bf = sb3[f];
            int cur = ssg[ps];
            float run = 0.f;
            for (int p = ps; p < pe; p++) {
                float phi = sbuf[p * PITCH + f] + bf;
                int sp = ssg[p];
                if (sp != cur) {
                    atomicAdd(&d_sums[cur * DOUT + f], run);
                    run = 0.f;
                    cur = sp;
                }
                run += phi;
            }
            atomicAdd(&d_sums[cur * DOUT + f], run);
        }
    }
}

__global__ void finalize_means(int Bn) {
    int i = blockIdx.x * blockDim.x + threadIdx.x;
    if (i < Bn * DOUT) {
        int b = i >> 7;
        float cnt = (float)(d_offs[b + 1] - d_offs[b]);
        d_emb[i] = d_sums[i] / cnt;
    }
}

__global__ void broadcast_out(float4* __restrict__ out, long long total4) {
    long long i = (long long)blockIdx.x * blockDim.x + threadIdx.x;
    if (i < total4) {
        long long p = i >> 5;
        int c = (int)(i & 31);
        const float4* emb4 = reinterpret_cast<const float4*>(d_emb);
        out[i] = emb4[(long long)d_seg[p] * 32 + c];
    }
}

extern "C" void kernel_launch(void* const* d_in, const int* in_sizes, int n_in,
                              void* d_out, int out_size) {
    const float* z   = (const float*)d_in[0];
    const float* W1  = (const float*)d_in[1];
    const float* b1  = (const float*)d_in[2];
    const float* g1  = (const float*)d_in[3];
    const float* be1 = (const float*)d_in[4];
    const float* W2  = (const float*)d_in[5];
    const float* b2  = (const float*)d_in[6];
    const float* g2  = (const float*)d_in[7];
    const float* be2 = (const float*)d_in[8];
    const float* W3  = (const float*)d_in[9];
    const float* b3  = (const float*)d_in[10];
    const void*  np  = d_in[11];

    const int Bn = in_sizes[11];
    const int N  = in_sizes[0] / DIN;

    static const size_t SMEM_BYTES =
        (MT * PITCH + MT * ZPITCH + 6 * HDIM + DOUT) * sizeof(float) + MT * sizeof(int);
    cudaFuncSetAttribute(mlp_mma, cudaFuncAttributeMaxDynamicSharedMemorySize,
                         (int)SMEM_BYTES);

    scan_offsets<<<1, 256>>>(np, Bn);
    fill_seg<<<Bn, 128>>>(Bn);
    zero_sums<<<(Bn * DOUT + 255) / 256, 256>>>(Bn * DOUT);
    cvt_weights<<<128, 256>>>(W1, W2, W3);

    const int tiles = (N + MT - 1) / MT;
    mlp_mma<<<tiles, TPB, SMEM_BYTES>>>(z, b1, g1, be1, b2, g2, be2, b3, N);

    finalize_means<<<(Bn * DOUT + 255) / 256, 256>>>(Bn);

    const long long total4 = (long long)N * (DOUT / 4);
    broadcast_out<<<(int)((total4 + 255) / 256), 256>>>((float4*)d_out, total4);
}

// round 6
// speedup vs baseline: 1.5810x; 1.1514x over previous
#include <cuda_runtime.h>

#define TPB    256
#define MT     64          // points per CTA
#define HDIM   256
#define DIN    16
#define DOUT   128
#define PITCH  260         // sbuf pitch: A-frag LDS conflict-free ((4g+tg)%32 distinct)
#define ZPITCH 20
#define BMAX   4096
#define NMAX   1100000

// ---------------- device scratch (no allocations allowed) ----------------
__device__ long long d_offs[BMAX + 1];
__device__ int       d_seg[NMAX];
__device__ float     d_sums[BMAX * DOUT];
__device__ float     d_emb[BMAX * DOUT];
// k-pair packed tf32 weights: index (koct*N + n)*4 + tg  ->  {W[8koct+tg][n], W[8koct+tg+4][n]}
__device__ float2    d_W1p[2  * HDIM * 4];
__device__ float2    d_W2p[32 * HDIM * 4];
__device__ float2    d_W3p[32 * DOUT * 4];

// ---------------- helpers ----------------
__device__ __forceinline__ float to_tf32(float x) {
    float r; asm("cvt.rna.tf32.f32 %0, %1;" : "=f"(r) : "f"(x)); return r;
}

__device__ __forceinline__ void mma_tf32(float4& d,
                                         unsigned a0, unsigned a1, unsigned a2, unsigned a3,
                                         unsigned b0, unsigned b1) {
    asm volatile(
        "mma.sync.aligned.m16n8k8.row.col.f32.tf32.tf32.f32 "
        "{%0,%1,%2,%3}, {%4,%5,%6,%7}, {%8,%9}, {%0,%1,%2,%3};"
        : "+f"(d.x), "+f"(d.y), "+f"(d.z), "+f"(d.w)
        : "r"(a0), "r"(a1), "r"(a2), "r"(a3), "r"(b0), "r"(b1));
}

__device__ __forceinline__ long long get_count(const void* np, int i, int is64) {
    if (is64) return ((const long long*)np)[i];
    return (long long)((const int*)np)[i];
}

// ---------------- small setup kernels ----------------
__global__ void scan_offsets(const void* __restrict__ np, int Bn) {
    __shared__ long long part[256];
    __shared__ int s_is64;
    if (threadIdx.x == 0) {
        const int* p32 = (const int*)np;
        int is64 = 1;
        for (int i = 1; i < 7 && i < 2 * Bn; i += 2)
            if (p32[i] != 0) is64 = 0;
        s_is64 = is64;
    }
    __syncthreads();
    const int is64 = s_is64;
    const int chunk = (Bn + 255) / 256;
    const int c0 = threadIdx.x * chunk;
    long long s = 0;
    for (int i = 0; i < chunk; i++) {
        int idx = c0 + i;
        if (idx < Bn) s += get_count(np, idx, is64);
    }
    part[threadIdx.x] = s;
    __syncthreads();
    if (threadIdx.x == 0) {
        long long r = 0;
        for (int i = 0; i < 256; i++) { long long t = part[i]; part[i] = r; r += t; }
    }
    __syncthreads();
    long long base = part[threadIdx.x];
    for (int i = 0; i < chunk; i++) {
        int idx = c0 + i;
        if (idx < Bn) {
            d_offs[idx] = base;
            base += get_count(np, idx, is64);
            if (idx == Bn - 1) d_offs[Bn] = base;
        }
    }
}

__global__ void fill_seg(int Bn) {
    int b = blockIdx.x;
    long long lo = d_offs[b], hi = d_offs[b + 1];
    for (long long i = lo + threadIdx.x; i < hi; i += blockDim.x)
        d_seg[i] = b;
}

__global__ void zero_sums(int n) {
    int i = blockIdx.x * blockDim.x + threadIdx.x;
    if (i < n) d_sums[i] = 0.f;
}

// pack + tf32-truncate weights into k-pair float2 layout
__global__ void cvt_weights(const float* __restrict__ W1,
                            const float* __restrict__ W2,
                            const float* __restrict__ W3) {
    int i = blockIdx.x * 256 + threadIdx.x;   // launched with 32768 threads
    if (i < 32 * HDIM * 4) {
        int tg = i & 3, n = (i >> 2) & (HDIM - 1), ko = i >> 10;
        d_W2p[i] = make_float2(to_tf32(W2[(8 * ko + tg) * HDIM + n]),
                               to_tf32(W2[(8 * ko + tg + 4) * HDIM + n]));
    }
    if (i < 32 * DOUT * 4) {
        int tg = i & 3, n = (i >> 2) & (DOUT - 1), ko = i >> 9;
        d_W3p[i] = make_float2(to_tf32(W3[(8 * ko + tg) * DOUT + n]),
                               to_tf32(W3[(8 * ko + tg + 4) * DOUT + n]));
    }
    if (i < 2 * HDIM * 4) {
        int tg = i & 3, n = (i >> 2) & (HDIM - 1), ko = i >> 10;
        d_W1p[i] = make_float2(to_tf32(W1[(8 * ko + tg) * HDIM + n]),
                               to_tf32(W1[(8 * ko + tg + 4) * HDIM + n]));
    }
}

// ---------------- in-register LN + ReLU ----------------
// acc[m][t]: {x,y}=row 16m+g cols n0+8t+2tg{,+1}; {z,w}=row 16m+g+8 same cols.
// Adds bias, computes LN stats via quad-shuffle + 64x8 smem partials,
// normalizes + ReLU + tf32 in regs, stores to sbuf (pitch PITCH) for next layer.
// 3 __syncthreads inside; all 256 threads must call.
__device__ __forceinline__ void ln_relu_reg(
    float4 (&acc)[4][4], float* __restrict__ sbuf,
    const float* __restrict__ bi, const float* __restrict__ ga, const float* __restrict__ be,
    float* __restrict__ red_s, float* __restrict__ red_q,
    float* __restrict__ s_m, float* __restrict__ s_r,
    int g, int tg, int n0, int warp, int tid)
{
    // bias add (column-wise, same for both row-halves)
    #pragma unroll
    for (int t = 0; t < 4; t++) {
        const float2 bb = *(const float2*)(bi + n0 + 8 * t + 2 * tg);
        #pragma unroll
        for (int m = 0; m < 4; m++) {
            acc[m][t].x += bb.x; acc[m][t].y += bb.y;
            acc[m][t].z += bb.x; acc[m][t].w += bb.y;
        }
    }
    // per-thread partial sums per row-slot
    float s[4][2], q[4][2];
    #pragma unroll
    for (int m = 0; m < 4; m++) {
        float sl = 0.f, ql = 0.f, sh = 0.f, qh = 0.f;
        #pragma unroll
        for (int t = 0; t < 4; t++) {
            float4 v = acc[m][t];
            sl += v.x + v.y;  ql += v.x * v.x + v.y * v.y;
            sh += v.z + v.w;  qh += v.z * v.z + v.w * v.w;
        }
        s[m][0] = sl; q[m][0] = ql; s[m][1] = sh; q[m][1] = qh;
    }
    // reduce over tg (adjacent lanes within quad)
    #pragma unroll
    for (int o = 1; o <= 2; o <<= 1) {
        #pragma unroll
        for (int m = 0; m < 4; m++) {
            #pragma unroll
            for (int h = 0; h < 2; h++) {
                s[m][h] += __shfl_xor_sync(0xffffffffu, s[m][h], o);
                q[m][h] += __shfl_xor_sync(0xffffffffu, q[m][h], o);
            }
        }
    }
    if (tg == 0) {
        #pragma unroll
        for (int m = 0; m < 4; m++) {
            red_s[(16 * m + g) * 8 + warp]     = s[m][0];
            red_q[(16 * m + g) * 8 + warp]     = q[m][0];
            red_s[(16 * m + g + 8) * 8 + warp] = s[m][1];
            red_q[(16 * m + g + 8) * 8 + warp] = q[m][1];
        }
    }
    __syncthreads();
    if (tid < MT) {
        float ss = 0.f, qq = 0.f;
        #pragma unroll
        for (int w = 0; w < 8; w++) { ss += red_s[tid * 8 + w]; qq += red_q[tid * 8 + w]; }
        float mm = ss * (1.f / 256.f);
        s_m[tid] = mm;
        s_r[tid] = rsqrtf(qq * (1.f / 256.f) - mm * mm + 1e-5f);
    }
    __syncthreads();
    #pragma unroll
    for (int m = 0; m < 4; m++) {
        const float ml = s_m[16 * m + g],     rl = s_r[16 * m + g];
        const float mh = s_m[16 * m + g + 8], rh = s_r[16 * m + g + 8];
        #pragma unroll
        for (int t = 0; t < 4; t++) {
            const int col = n0 + 8 * t + 2 * tg;
            const float2 gg = *(const float2*)(ga + col);
            const float2 ee = *(const float2*)(be + col);
            float2 lo, hi;
            lo.x = to_tf32(fmaxf((acc[m][t].x - ml) * rl * gg.x + ee.x, 0.f));
            lo.y = to_tf32(fmaxf((acc[m][t].y - ml) * rl * gg.y + ee.y, 0.f));
            hi.x = to_tf32(fmaxf((acc[m][t].z - mh) * rh * gg.x + ee.x, 0.f));
            hi.y = to_tf32(fmaxf((acc[m][t].w - mh) * rh * gg.y + ee.y, 0.f));
            *(float2*)(sbuf + (16 * m + g) * PITCH + col)     = lo;
            *(float2*)(sbuf + (16 * m + g + 8) * PITCH + col) = hi;
        }
    }
    __syncthreads();
}

// ---------------- main fused kernel ----------------
__global__ __launch_bounds__(TPB, 2)
void mlp_mma(const float* __restrict__ z,
             const float* __restrict__ b1, const float* __restrict__ g1, const float* __restrict__ be1,
             const float* __restrict__ b2, const float* __restrict__ g2, const float* __restrict__ be2,
             const float* __restrict__ b3,
             int Npts)
{
    extern __shared__ char smem_raw[];
    float* sbuf  = (float*)smem_raw;                // 64*PITCH
    float* zs    = sbuf + MT * PITCH;               // 64*ZPITCH
    float* sb1   = zs + MT * ZPITCH;
    float* sg1   = sb1 + HDIM;
    float* sbe1  = sg1 + HDIM;
    float* sb2   = sbe1 + HDIM;
    float* sg2   = sb2 + HDIM;
    float* sbe2  = sg2 + HDIM;
    float* sb3   = sbe2 + HDIM;                     // 128
    float* red_s = sb3 + DOUT;                      // 512
    float* red_q = red_s + 512;                     // 512
    float* s_m   = red_q + 512;                     // 64
    float* s_r   = s_m + MT;                        // 64
    int*   ssg   = (int*)(s_r + MT);                // 64

    const int tid = threadIdx.x;
    const int p0 = blockIdx.x * MT;
    const int npts = min(MT, Npts - p0);
    if (npts <= 0) return;

    const int warp = tid >> 5, lane = tid & 31;
    const int g = lane >> 2, tg = lane & 3;
    const int n0 = warp * 32;                       // 32-col slice for H=256 layers
    const int n3 = warp * 16;                       // 16-col slice for DOUT=128

    // ---- preload W1 into regs while smem fills ----
    float2 w1p[2][4];
    #pragma unroll
    for (int ks = 0; ks < 2; ks++)
        #pragma unroll
        for (int t = 0; t < 4; t++)
            w1p[ks][t] = d_W1p[(ks * HDIM + n0 + 8 * t + g) * 4 + tg];

    {
        const float4* z4 = (const float4*)(z + (long long)p0 * DIN);
        int pi = tid >> 2, ci = tid & 3;
        float4 v = make_float4(0.f, 0.f, 0.f, 0.f);
        if (pi < npts) v = z4[pi * 4 + ci];
        float* zr = zs + pi * ZPITCH + 4 * ci;
        zr[0] = to_tf32(v.x); zr[1] = to_tf32(v.y); zr[2] = to_tf32(v.z); zr[3] = to_tf32(v.w);

        sb1[tid] = b1[tid]; sg1[tid] = g1[tid]; sbe1[tid] = be1[tid];
        sb2[tid] = b2[tid]; sg2[tid] = g2[tid]; sbe2[tid] = be2[tid];
        if (tid < DOUT) sb3[tid] = b3[tid];
        if (tid < MT) ssg[tid] = (tid < npts) ? d_seg[p0 + tid] : 0;
    }
    __syncthreads();

    float2 bw0[4], bw1[4];   // B-fragment pipeline registers
    float4 acc[4][4];

    // ================= Layer 1: [64x16] @ [16x256] =================
    #pragma unroll
    for (int m = 0; m < 4; m++)
        #pragma unroll
        for (int t = 0; t < 4; t++) acc[m][t] = make_float4(0.f, 0.f, 0.f, 0.f);

    #pragma unroll
    for (int ks = 0; ks < 2; ks++) {
        const int k = 8 * ks;
        unsigned a[4][4];
        #pragma unroll
        for (int m = 0; m < 4; m++) {
            const float* ar = zs + (16 * m + g) * ZPITCH + k + tg;
            a[m][0] = __float_as_uint(ar[0]);
            a[m][1] = __float_as_uint(ar[8 * ZPITCH]);
            a[m][2] = __float_as_uint(ar[4]);
            a[m][3] = __float_as_uint(ar[8 * ZPITCH + 4]);
        }
        #pragma unroll
        for (int t = 0; t < 4; t++)
            #pragma unroll
            for (int m = 0; m < 4; m++)
                mma_tf32(acc[m][t], a[m][0], a[m][1], a[m][2], a[m][3],
                         __float_as_uint(w1p[ks][t].x), __float_as_uint(w1p[ks][t].y));
    }
    // preload layer-2 chunk 0 (L2 latency hidden under LN1)
    #pragma unroll
    for (int t = 0; t < 4; t++)
        bw0[t] = d_W2p[(n0 + 8 * t + g) * 4 + tg];

    ln_relu_reg(acc, sbuf, sb1, sg1, sbe1, red_s, red_q, s_m, s_r, g, tg, n0, warp, tid);

    // ================= Layer 2: [64x256] @ [256x256], reg-pipelined =================
    #pragma unroll
    for (int m = 0; m < 4; m++)
        #pragma unroll
        for (int t = 0; t < 4; t++) acc[m][t] = make_float4(0.f, 0.f, 0.f, 0.f);

    #pragma unroll 1
    for (int c = 0; c < 32; c += 2) {
        #pragma unroll
        for (int t = 0; t < 4; t++)
            bw1[t] = d_W2p[((c + 1) * HDIM + n0 + 8 * t + g) * 4 + tg];
        {
            const int k = 8 * c;
            unsigned a[4][4];
            #pragma unroll
            for (int m = 0; m < 4; m++) {
                const float* ar = sbuf + (16 * m + g) * PITCH + k + tg;
                a[m][0] = __float_as_uint(ar[0]);
                a[m][1] = __float_as_uint(ar[8 * PITCH]);
                a[m][2] = __float_as_uint(ar[4]);
                a[m][3] = __float_as_uint(ar[8 * PITCH + 4]);
            }
            #pragma unroll
            for (int t = 0; t < 4; t++)
                #pragma unroll
                for (int m = 0; m < 4; m++)
                    mma_tf32(acc[m][t], a[m][0], a[m][1], a[m][2], a[m][3],
                             __float_as_uint(bw0[t].x), __float_as_uint(bw0[t].y));
        }
        if (c + 2 < 32) {
            #pragma unroll
            for (int t = 0; t < 4; t++)
                bw0[t] = d_W2p[((c + 2) * HDIM + n0 + 8 * t + g) * 4 + tg];
        }
        {
            const int k = 8 * (c + 1);
            unsigned a[4][4];
            #pragma unroll
            for (int m = 0; m < 4; m++) {
                const float* ar = sbuf + (16 * m + g) * PITCH + k + tg;
                a[m][0] = __float_as_uint(ar[0]);
                a[m][1] = __float_as_uint(ar[8 * PITCH]);
                a[m][2] = __float_as_uint(ar[4]);
                a[m][3] = __float_as_uint(ar[8 * PITCH + 4]);
            }
            #pragma unroll
            for (int t = 0; t < 4; t++)
                #pragma unroll
                for (int m = 0; m < 4; m++)
                    mma_tf32(acc[m][t], a[m][0], a[m][1], a[m][2], a[m][3],
                             __float_as_uint(bw1[t].x), __float_as_uint(bw1[t].y));
        }
    }
    // preload layer-3 chunk 0 (hidden under LN2)
    #pragma unroll
    for (int t = 0; t < 2; t++)
        bw0[t] = d_W3p[(n3 + 8 * t + g) * 4 + tg];

    // barrier inside ln_relu_reg (#1) also guarantees all warps finished reading sbuf
    ln_relu_reg(acc, sbuf, sb2, sg2, sbe2, red_s, red_q, s_m, s_r, g, tg, n0, warp, tid);

    // ================= Layer 3: [64x256] @ [256x128], reg-pipelined =================
    {
        float4 acc3[4][2];
        #pragma unroll
        for (int m = 0; m < 4; m++)
            #pragma unroll
            for (int t = 0; t < 2; t++) acc3[m][t] = make_float4(0.f, 0.f, 0.f, 0.f);

        #pragma unroll 1
        for (int c = 0; c < 32; c += 2) {
            #pragma unroll
            for (int t = 0; t < 2; t++)
                bw1[t] = d_W3p[((c + 1) * DOUT + n3 + 8 * t + g) * 4 + tg];
            {
                const int k = 8 * c;
                unsigned a[4][4];
                #pragma unroll
                for (int m = 0; m < 4; m++) {
                    const float* ar = sbuf + (16 * m + g) * PITCH + k + tg;
                    a[m][0] = __float_as_uint(ar[0]);
                    a[m][1] = __float_as_uint(ar[8 * PITCH]);
                    a[m][2] = __float_as_uint(ar[4]);
                    a[m][3] = __float_as_uint(ar[8 * PITCH + 4]);
                }
                #pragma unroll
                for (int t = 0; t < 2; t++)
                    #pragma unroll
                    for (int m = 0; m < 4; m++)
                        mma_tf32(acc3[m][t], a[m][0], a[m][1], a[m][2], a[m][3],
                                 __float_as_uint(bw0[t].x), __float_as_uint(bw0[t].y));
            }
            if (c + 2 < 32) {
                #pragma unroll
                for (int t = 0; t < 2; t++)
                    bw0[t] = d_W3p[((c + 2) * DOUT + n3 + 8 * t + g) * 4 + tg];
            }
            {
                const int k = 8 * (c + 1);
                unsigned a[4][4];
                #pragma unroll
                for (int m = 0; m < 4; m++) {
                    const float* ar = sbuf + (16 * m + g) * PITCH + k + tg;
                    a[m][0] = __float_as_uint(ar[0]);
                    a[m][1] = __float_as_uint(ar[8 * PITCH]);
                    a[m][2] = __float_as_uint(ar[4]);
                    a[m][3] = __float_as_uint(ar[8 * PITCH + 4]);
                }
                #pragma unroll
                for (int t = 0; t < 2; t++)
                    #pragma unroll
                    for (int m = 0; m < 4; m++)
                        mma_tf32(acc3[m][t], a[m][0], a[m][1], a[m][2], a[m][3],
                                 __float_as_uint(bw1[t].x), __float_as_uint(bw1[t].y));
            }
        }
        __syncthreads();   // all sbuf A reads done before overwriting with C3
        #pragma unroll
        for (int m = 0; m < 4; m++)
            #pragma unroll
            for (int t = 0; t < 2; t++) {
                float* cr = sbuf + (16 * m + g) * PITCH + n3 + 8 * t + 2 * tg;
                cr[0] = acc3[m][t].x; cr[1] = acc3[m][t].y;
                cr[8 * PITCH] = acc3[m][t].z; cr[8 * PITCH + 1] = acc3[m][t].w;
            }
    }
    __syncthreads();

    // ================= epilogue: bias + run-length segment accumulate =================
    {
        const int f = tid & (DOUT - 1);
        const int half = tid >> 7;
        const int ps = half * 32;
        const int pe = min(ps + 32, npts);
        if (ps < pe) {
            const float bf = sb3[f];
            int cur = ssg[ps];
            float run = 0.f;
            for (int p = ps; p < pe; p++) {
                float phi = sbuf[p * PITCH + f] + bf;
                int sp = ssg[p];
                if (sp != cur) {
                    atomicAdd(&d_sums[cur * DOUT + f], run);
                    run = 0.f;
                    cur = sp;
                }
                run += phi;
            }
            atomicAdd(&d_sums[cur * DOUT + f], run);
        }
    }
}

__global__ void finalize_means(int Bn) {
    int i = blockIdx.x * blockDim.x + threadIdx.x;
    if (i < Bn * DOUT) {
        int b = i >> 7;
        float cnt = (float)(d_offs[b + 1] - d_offs[b]);
        d_emb[i] = d_sums[i] / cnt;
    }
}

__global__ void broadcast_out(float4* __restrict__ out, long long total4) {
    long long i = (long long)blockIdx.x * blockDim.x + threadIdx.x;
    if (i < total4) {
        long long p = i >> 5;
        int c = (int)(i & 31);
        const float4* emb4 = reinterpret_cast<const float4*>(d_emb);
        out[i] = emb4[(long long)d_seg[p] * 32 + c];
    }
}

extern "C" void kernel_launch(void* const* d_in, const int* in_sizes, int n_in,
                              void* d_out, int out_size) {
    const float* z   = (const float*)d_in[0];
    const float* W1  = (const float*)d_in[1];
    const float* b1  = (const float*)d_in[2];
    const float* g1  = (const float*)d_in[3];
    const float* be1 = (const float*)d_in[4];
    const float* W2  = (const float*)d_in[5];
    const float* b2  = (const float*)d_in[6];
    const float* g2  = (const float*)d_in[7];
    const float* be2 = (const float*)d_in[8];
    const float* W3  = (const float*)d_in[9];
    const float* b3  = (const float*)d_in[10];
    const void*  np  = d_in[11];

    const int Bn = in_sizes[11];
    const int N  = in_sizes[0] / DIN;

    static const size_t SMEM_BYTES =
        (MT * PITCH + MT * ZPITCH + 6 * HDIM + DOUT + 512 + 512 + 2 * MT) * sizeof(float)
        + MT * sizeof(int);
    cudaFuncSetAttribute(mlp_mma, cudaFuncAttributeMaxDynamicSharedMemorySize,
                         (int)SMEM_BYTES);

    scan_offsets<<<1, 256>>>(np, Bn);
    fill_seg<<<Bn, 128>>>(Bn);
    zero_sums<<<(Bn * DOUT + 255) / 256, 256>>>(Bn * DOUT);
    cvt_weights<<<128, 256>>>(W1, W2, W3);

    const int tiles = (N + MT - 1) / MT;
    mlp_mma<<<tiles, TPB, SMEM_BYTES>>>(z, b1, g1, be1, b2, g2, be2, b3, N);

    finalize_means<<<(Bn * DOUT + 255) / 256, 256>>>(Bn);

    const long long total4 = (long long)N * (DOUT / 4);
    broadcast_out<<<(int)((total4 + 255) / 256), 256>>>((float4*)d_out, total4);
}

// round 7
// speedup vs baseline: 2.4487x; 1.5488x over previous
#include <cuda_runtime.h>
#include <cuda_fp16.h>

#define TPB    256
#define MT     64          // points per CTA
#define HDIM   256
#define DIN    16
#define DOUT   128
#define PITCHH 264         // sbuf pitch in halves; word-stride 132 % 32 == 4 -> conflict-free frags
#define FPITCH 132         // float view pitch for layer-3 C / epilogue
#define ZPH    24          // z tile pitch in halves (word-stride 12 -> conflict-free)
#define BMAX   4096
#define NMAX   1100000

// ---------------- device scratch (no allocations allowed) ----------------
__device__ long long d_offs[BMAX + 1];
__device__ int       d_seg[NMAX];
__device__ float     d_sums[BMAX * DOUT];
__device__ float     d_emb[BMAX * DOUT];
// fp16 k16-chunk packed weights: index (kc*N + n)*4 + tg -> uint2
//   .x = {W[16kc+2tg][n], W[16kc+2tg+1][n]}   .y = {W[16kc+8+2tg][n], W[16kc+8+2tg+1][n]}
__device__ uint2     d_W1h[1  * HDIM * 4];
__device__ uint2     d_W2h[16 * HDIM * 4];
__device__ uint2     d_W3h[16 * DOUT * 4];

// ---------------- helpers ----------------
__device__ __forceinline__ unsigned h2u(float a, float b) {
    __half2 h = __floats2half2_rn(a, b);
    return *reinterpret_cast<unsigned*>(&h);
}

__device__ __forceinline__ void mma_f16(float4& d,
                                        unsigned a0, unsigned a1, unsigned a2, unsigned a3,
                                        unsigned b0, unsigned b1) {
    asm volatile(
        "mma.sync.aligned.m16n8k16.row.col.f32.f16.f16.f32 "
        "{%0,%1,%2,%3}, {%4,%5,%6,%7}, {%8,%9}, {%0,%1,%2,%3};"
        : "+f"(d.x), "+f"(d.y), "+f"(d.z), "+f"(d.w)
        : "r"(a0), "r"(a1), "r"(a2), "r"(a3), "r"(b0), "r"(b1));
}

__device__ __forceinline__ long long get_count(const void* np, int i, int is64) {
    if (is64) return ((const long long*)np)[i];
    return (long long)((const int*)np)[i];
}

// ---------------- small setup kernels ----------------
__global__ void scan_offsets(const void* __restrict__ np, int Bn) {
    __shared__ long long part[256];
    __shared__ int s_is64;
    if (threadIdx.x == 0) {
        const int* p32 = (const int*)np;
        int is64 = 1;
        for (int i = 1; i < 7 && i < 2 * Bn; i += 2)
            if (p32[i] != 0) is64 = 0;
        s_is64 = is64;
    }
    __syncthreads();
    const int is64 = s_is64;
    const int chunk = (Bn + 255) / 256;
    const int c0 = threadIdx.x * chunk;
    long long s = 0;
    for (int i = 0; i < chunk; i++) {
        int idx = c0 + i;
        if (idx < Bn) s += get_count(np, idx, is64);
    }
    part[threadIdx.x] = s;
    __syncthreads();
    if (threadIdx.x == 0) {
        long long r = 0;
        for (int i = 0; i < 256; i++) { long long t = part[i]; part[i] = r; r += t; }
    }
    __syncthreads();
    long long base = part[threadIdx.x];
    for (int i = 0; i < chunk; i++) {
        int idx = c0 + i;
        if (idx < Bn) {
            d_offs[idx] = base;
            base += get_count(np, idx, is64);
            if (idx == Bn - 1) d_offs[Bn] = base;
        }
    }
}

__global__ void fill_seg(int Bn) {
    int b = blockIdx.x;
    long long lo = d_offs[b], hi = d_offs[b + 1];
    for (long long i = lo + threadIdx.x; i < hi; i += blockDim.x)
        d_seg[i] = b;
}

__global__ void zero_sums(int n) {
    int i = blockIdx.x * blockDim.x + threadIdx.x;
    if (i < n) d_sums[i] = 0.f;
}

// pack weights into fp16 k16-chunk layout
__global__ void cvt_weights(const float* __restrict__ W1,
                            const float* __restrict__ W2,
                            const float* __restrict__ W3) {
    int i = blockIdx.x * 256 + threadIdx.x;   // launch >= 16384 threads
    if (i < 16 * HDIM * 4) {
        int tg = i & 3, n = (i >> 2) & (HDIM - 1), kc = i >> 10;
        int k = 16 * kc + 2 * tg;
        d_W2h[i] = make_uint2(h2u(W2[k * HDIM + n],       W2[(k + 1) * HDIM + n]),
                              h2u(W2[(k + 8) * HDIM + n], W2[(k + 9) * HDIM + n]));
    }
    if (i < 16 * DOUT * 4) {
        int tg = i & 3, n = (i >> 2) & (DOUT - 1), kc = i >> 9;
        int k = 16 * kc + 2 * tg;
        d_W3h[i] = make_uint2(h2u(W3[k * DOUT + n],       W3[(k + 1) * DOUT + n]),
                              h2u(W3[(k + 8) * DOUT + n], W3[(k + 9) * DOUT + n]));
    }
    if (i < 1 * HDIM * 4) {
        int tg = i & 3, n = i >> 2;
        int k = 2 * tg;
        d_W1h[i] = make_uint2(h2u(W1[k * HDIM + n],       W1[(k + 1) * HDIM + n]),
                              h2u(W1[(k + 8) * HDIM + n], W1[(k + 9) * HDIM + n]));
    }
}

// ---------------- in-register LN + ReLU -> fp16 smem ----------------
// acc[m][t]: {x,y}=row 16m+g cols n0+8t+2tg{,+1}; {z,w}=row 16m+g+8 same cols.
__device__ __forceinline__ void ln_relu_reg(
    float4 (&acc)[4][4], __half* __restrict__ sbufh,
    const float* __restrict__ bi, const float* __restrict__ ga, const float* __restrict__ be,
    float* __restrict__ red_s, float* __restrict__ red_q,
    float* __restrict__ s_m, float* __restrict__ s_r,
    int g, int tg, int n0, int warp, int tid)
{
    #pragma unroll
    for (int t = 0; t < 4; t++) {
        const float2 bb = *(const float2*)(bi + n0 + 8 * t + 2 * tg);
        #pragma unroll
        for (int m = 0; m < 4; m++) {
            acc[m][t].x += bb.x; acc[m][t].y += bb.y;
            acc[m][t].z += bb.x; acc[m][t].w += bb.y;
        }
    }
    float s[4][2], q[4][2];
    #pragma unroll
    for (int m = 0; m < 4; m++) {
        float sl = 0.f, ql = 0.f, sh = 0.f, qh = 0.f;
        #pragma unroll
        for (int t = 0; t < 4; t++) {
            float4 v = acc[m][t];
            sl += v.x + v.y;  ql += v.x * v.x + v.y * v.y;
            sh += v.z + v.w;  qh += v.z * v.z + v.w * v.w;
        }
        s[m][0] = sl; q[m][0] = ql; s[m][1] = sh; q[m][1] = qh;
    }
    #pragma unroll
    for (int o = 1; o <= 2; o <<= 1) {
        #pragma unroll
        for (int m = 0; m < 4; m++) {
            #pragma unroll
            for (int h = 0; h < 2; h++) {
                s[m][h] += __shfl_xor_sync(0xffffffffu, s[m][h], o);
                q[m][h] += __shfl_xor_sync(0xffffffffu, q[m][h], o);
            }
        }
    }
    if (tg == 0) {
        #pragma unroll
        for (int m = 0; m < 4; m++) {
            red_s[(16 * m + g) * 8 + warp]     = s[m][0];
            red_q[(16 * m + g) * 8 + warp]     = q[m][0];
            red_s[(16 * m + g + 8) * 8 + warp] = s[m][1];
            red_q[(16 * m + g + 8) * 8 + warp] = q[m][1];
        }
    }
    __syncthreads();
    if (tid < MT) {
        float ss = 0.f, qq = 0.f;
        #pragma unroll
        for (int w = 0; w < 8; w++) { ss += red_s[tid * 8 + w]; qq += red_q[tid * 8 + w]; }
        float mm = ss * (1.f / 256.f);
        s_m[tid] = mm;
        s_r[tid] = rsqrtf(qq * (1.f / 256.f) - mm * mm + 1e-5f);
    }
    __syncthreads();
    #pragma unroll
    for (int m = 0; m < 4; m++) {
        const float ml = s_m[16 * m + g],     rl = s_r[16 * m + g];
        const float mh = s_m[16 * m + g + 8], rh = s_r[16 * m + g + 8];
        #pragma unroll
        for (int t = 0; t < 4; t++) {
            const int col = n0 + 8 * t + 2 * tg;
            const float2 gg = *(const float2*)(ga + col);
            const float2 ee = *(const float2*)(be + col);
            unsigned lo = h2u(fmaxf((acc[m][t].x - ml) * rl * gg.x + ee.x, 0.f),
                              fmaxf((acc[m][t].y - ml) * rl * gg.y + ee.y, 0.f));
            unsigned hi = h2u(fmaxf((acc[m][t].z - mh) * rh * gg.x + ee.x, 0.f),
                              fmaxf((acc[m][t].w - mh) * rh * gg.y + ee.y, 0.f));
            *(unsigned*)(sbufh + (16 * m + g) * PITCHH + col)     = lo;
            *(unsigned*)(sbufh + (16 * m + g + 8) * PITCHH + col) = hi;
        }
    }
    __syncthreads();
}

// ---------------- main fused kernel ----------------
__global__ __launch_bounds__(TPB, 2)
void mlp_mma(const float* __restrict__ z,
             const float* __restrict__ b1, const float* __restrict__ g1, const float* __restrict__ be1,
             const float* __restrict__ b2, const float* __restrict__ g2, const float* __restrict__ be2,
             const float* __restrict__ b3,
             int Npts)
{
    extern __shared__ char smem_raw[];
    __half* sbufh = (__half*)smem_raw;              // 64*PITCHH halves
    __half* zsh   = sbufh + MT * PITCHH;            // 64*ZPH halves
    float* sb1   = (float*)(zsh + MT * ZPH);
    float* sg1   = sb1 + HDIM;
    float* sbe1  = sg1 + HDIM;
    float* sb2   = sbe1 + HDIM;
    float* sg2   = sb2 + HDIM;
    float* sbe2  = sg2 + HDIM;
    float* sb3   = sbe2 + HDIM;                     // 128
    float* red_s = sb3 + DOUT;                      // 512
    float* red_q = red_s + 512;                     // 512
    float* s_m   = red_q + 512;                     // 64
    float* s_r   = s_m + MT;                        // 64
    int*   ssg   = (int*)(s_r + MT);                // 64
    float* fbuf  = (float*)smem_raw;                // layer-3 C view, pitch FPITCH

    const int tid = threadIdx.x;
    const int p0 = blockIdx.x * MT;
    const int npts = min(MT, Npts - p0);
    if (npts <= 0) return;

    const int warp = tid >> 5, lane = tid & 31;
    const int g = lane >> 2, tg = lane & 3;
    const int n0 = warp * 32;                       // 32-col slice for H=256 layers
    const int n3 = warp * 16;                       // 16-col slice for DOUT=128

    // ---- preload W1 fragments while smem fills ----
    uint2 w1h[4];
    #pragma unroll
    for (int t = 0; t < 4; t++)
        w1h[t] = d_W1h[(n0 + 8 * t + g) * 4 + tg];

    {
        const float4* z4 = (const float4*)(z + (long long)p0 * DIN);
        int pi = tid >> 2, ci = tid & 3;
        float4 v = make_float4(0.f, 0.f, 0.f, 0.f);
        if (pi < npts) v = z4[pi * 4 + ci];
        unsigned u0 = h2u(v.x, v.y), u1 = h2u(v.z, v.w);
        *(uint2*)(zsh + pi * ZPH + 4 * ci) = make_uint2(u0, u1);

        sb1[tid] = b1[tid]; sg1[tid] = g1[tid]; sbe1[tid] = be1[tid];
        sb2[tid] = b2[tid]; sg2[tid] = g2[tid]; sbe2[tid] = be2[tid];
        if (tid < DOUT) sb3[tid] = b3[tid];
        if (tid < MT) ssg[tid] = (tid < npts) ? d_seg[p0 + tid] : 0;
    }
    __syncthreads();

    uint2 bw0[4], bw1[4];   // B-fragment pipeline registers
    float4 acc[4][4];

    // ================= Layer 1: [64x16] @ [16x256], single k16 chunk =================
    #pragma unroll
    for (int m = 0; m < 4; m++)
        #pragma unroll
        for (int t = 0; t < 4; t++) acc[m][t] = make_float4(0.f, 0.f, 0.f, 0.f);

    {
        unsigned a[4][4];
        #pragma unroll
        for (int m = 0; m < 4; m++) {
            const __half* ar = zsh + (16 * m + g) * ZPH + 2 * tg;
            a[m][0] = *(const unsigned*)(ar);
            a[m][1] = *(const unsigned*)(ar + 8 * ZPH);
            a[m][2] = *(const unsigned*)(ar + 8);
            a[m][3] = *(const unsigned*)(ar + 8 * ZPH + 8);
        }
        #pragma unroll
        for (int t = 0; t < 4; t++)
            #pragma unroll
            for (int m = 0; m < 4; m++)
                mma_f16(acc[m][t], a[m][0], a[m][1], a[m][2], a[m][3],
                        w1h[t].x, w1h[t].y);
    }
    // preload layer-2 chunk 0 (L2 latency hidden under LN1)
    #pragma unroll
    for (int t = 0; t < 4; t++)
        bw0[t] = d_W2h[(n0 + 8 * t + g) * 4 + tg];

    ln_relu_reg(acc, sbufh, sb1, sg1, sbe1, red_s, red_q, s_m, s_r, g, tg, n0, warp, tid);

    // ================= Layer 2: [64x256] @ [256x256], 16 k16 chunks, reg-pipelined =================
    #pragma unroll
    for (int m = 0; m < 4; m++)
        #pragma unroll
        for (int t = 0; t < 4; t++) acc[m][t] = make_float4(0.f, 0.f, 0.f, 0.f);

    #pragma unroll 1
    for (int c = 0; c < 16; c += 2) {
        #pragma unroll
        for (int t = 0; t < 4; t++)
            bw1[t] = d_W2h[((c + 1) * HDIM + n0 + 8 * t + g) * 4 + tg];
        {
            const int k = 16 * c;
            unsigned a[4][4];
            #pragma unroll
            for (int m = 0; m < 4; m++) {
                const __half* ar = sbufh + (16 * m + g) * PITCHH + k + 2 * tg;
                a[m][0] = *(const unsigned*)(ar);
                a[m][1] = *(const unsigned*)(ar + 8 * PITCHH);
                a[m][2] = *(const unsigned*)(ar + 8);
                a[m][3] = *(const unsigned*)(ar + 8 * PITCHH + 8);
            }
            #pragma unroll
            for (int t = 0; t < 4; t++)
                #pragma unroll
                for (int m = 0; m < 4; m++)
                    mma_f16(acc[m][t], a[m][0], a[m][1], a[m][2], a[m][3],
                            bw0[t].x, bw0[t].y);
        }
        if (c + 2 < 16) {
            #pragma unroll
            for (int t = 0; t < 4; t++)
                bw0[t] = d_W2h[((c + 2) * HDIM + n0 + 8 * t + g) * 4 + tg];
        }
        {
            const int k = 16 * (c + 1);
            unsigned a[4][4];
            #pragma unroll
            for (int m = 0; m < 4; m++) {
                const __half* ar = sbufh + (16 * m + g) * PITCHH + k + 2 * tg;
                a[m][0] = *(const unsigned*)(ar);
                a[m][1] = *(const unsigned*)(ar + 8 * PITCHH);
                a[m][2] = *(const unsigned*)(ar + 8);
                a[m][3] = *(const unsigned*)(ar + 8 * PITCHH + 8);
            }
            #pragma unroll
            for (int t = 0; t < 4; t++)
                #pragma unroll
                for (int m = 0; m < 4; m++)
                    mma_f16(acc[m][t], a[m][0], a[m][1], a[m][2], a[m][3],
                            bw1[t].x, bw1[t].y);
        }
    }
    // preload layer-3 chunk 0 (hidden under LN2)
    #pragma unroll
    for (int t = 0; t < 2; t++)
        bw0[t] = d_W3h[(n3 + 8 * t + g) * 4 + tg];

    ln_relu_reg(acc, sbufh, sb2, sg2, sbe2, red_s, red_q, s_m, s_r, g, tg, n0, warp, tid);

    // ================= Layer 3: [64x256] @ [256x128], reg-pipelined =================
    {
        float4 acc3[4][2];
        #pragma unroll
        for (int m = 0; m < 4; m++)
            #pragma unroll
            for (int t = 0; t < 2; t++) acc3[m][t] = make_float4(0.f, 0.f, 0.f, 0.f);

        #pragma unroll 1
        for (int c = 0; c < 16; c += 2) {
            #pragma unroll
            for (int t = 0; t < 2; t++)
                bw1[t] = d_W3h[((c + 1) * DOUT + n3 + 8 * t + g) * 4 + tg];
            {
                const int k = 16 * c;
                unsigned a[4][4];
                #pragma unroll
                for (int m = 0; m < 4; m++) {
                    const __half* ar = sbufh + (16 * m + g) * PITCHH + k + 2 * tg;
                    a[m][0] = *(const unsigned*)(ar);
                    a[m][1] = *(const unsigned*)(ar + 8 * PITCHH);
                    a[m][2] = *(const unsigned*)(ar + 8);
                    a[m][3] = *(const unsigned*)(ar + 8 * PITCHH + 8);
                }
                #pragma unroll
                for (int t = 0; t < 2; t++)
                    #pragma unroll
                    for (int m = 0; m < 4; m++)
                        mma_f16(acc3[m][t], a[m][0], a[m][1], a[m][2], a[m][3],
                                bw0[t].x, bw0[t].y);
            }
            if (c + 2 < 16) {
                #pragma unroll
                for (int t = 0; t < 2; t++)
                    bw0[t] = d_W3h[((c + 2) * DOUT + n3 + 8 * t + g) * 4 + tg];
            }
            {
                const int k = 16 * (c + 1);
                unsigned a[4][4];
                #pragma unroll
                for (int m = 0; m < 4; m++) {
                    const __half* ar = sbufh + (16 * m + g) * PITCHH + k + 2 * tg;
                    a[m][0] = *(const unsigned*)(ar);
                    a[m][1] = *(const unsigned*)(ar + 8 * PITCHH);
                    a[m][2] = *(const unsigned*)(ar + 8);
                    a[m][3] = *(const unsigned*)(ar + 8 * PITCHH + 8);
                }
                #pragma unroll
                for (int t = 0; t < 2; t++)
                    #pragma unroll
                    for (int m = 0; m < 4; m++)
                        mma_f16(acc3[m][t], a[m][0], a[m][1], a[m][2], a[m][3],
                                bw1[t].x, bw1[t].y);
            }
        }
        __syncthreads();   // all sbuf A reads done before overwriting with C3 (float view)
        #pragma unroll
        for (int m = 0; m < 4; m++)
            #pragma unroll
            for (int t = 0; t < 2; t++) {
                float* cr = fbuf + (16 * m + g) * FPITCH + n3 + 8 * t + 2 * tg;
                cr[0] = acc3[m][t].x; cr[1] = acc3[m][t].y;
                cr[8 * FPITCH] = acc3[m][t].z; cr[8 * FPITCH + 1] = acc3[m][t].w;
            }
    }
    __syncthreads();

    // ================= epilogue: bias + run-length segment accumulate =================
    {
        const int f = tid & (DOUT - 1);
        const int half = tid >> 7;
        const int ps = half * 32;
        const int pe = min(ps + 32, npts);
        if (ps < pe) {
            const float bf = sb3[f];
            int cur = ssg[ps];
            float run = 0.f;
            for (int p = ps; p < pe; p++) {
                float phi = fbuf[p * FPITCH + f] + bf;
                int sp = ssg[p];
                if (sp != cur) {
                    atomicAdd(&d_sums[cur * DOUT + f], run);
                    run = 0.f;
                    cur = sp;
                }
                run += phi;
            }
            atomicAdd(&d_sums[cur * DOUT + f], run);
        }
    }
}

__global__ void finalize_means(int Bn) {
    int i = blockIdx.x * blockDim.x + threadIdx.x;
    if (i < Bn * DOUT) {
        int b = i >> 7;
        float cnt = (float)(d_offs[b + 1] - d_offs[b]);
        d_emb[i] = d_sums[i] / cnt;
    }
}

__global__ void broadcast_out(float4* __restrict__ out, long long total4) {
    long long i = (long long)blockIdx.x * blockDim.x + threadIdx.x;
    if (i < total4) {
        long long p = i >> 5;
        int c = (int)(i & 31);
        const float4* emb4 = reinterpret_cast<const float4*>(d_emb);
        out[i] = emb4[(long long)d_seg[p] * 32 + c];
    }
}

extern "C" void kernel_launch(void* const* d_in, const int* in_sizes, int n_in,
                              void* d_out, int out_size) {
    const float* z   = (const float*)d_in[0];
    const float* W1  = (const float*)d_in[1];
    const float* b1  = (const float*)d_in[2];
    const float* g1  = (const float*)d_in[3];
    const float* be1 = (const float*)d_in[4];
    const float* W2  = (const float*)d_in[5];
    const float* b2  = (const float*)d_in[6];
    const float* g2  = (const float*)d_in[7];
    const float* be2 = (const float*)d_in[8];
    const float* W3  = (const float*)d_in[9];
    const float* b3  = (const float*)d_in[10];
    const void*  np  = d_in[11];

    const int Bn = in_sizes[11];
    const int N  = in_sizes[0] / DIN;

    static const size_t SMEM_BYTES =
        (MT * PITCHH + MT * ZPH) * sizeof(__half)
        + (6 * HDIM + DOUT + 512 + 512 + 2 * MT) * sizeof(float)
        + MT * sizeof(int);
    cudaFuncSetAttribute(mlp_mma, cudaFuncAttributeMaxDynamicSharedMemorySize,
                         (int)SMEM_BYTES);

    scan_offsets<<<1, 256>>>(np, Bn);
    fill_seg<<<Bn, 128>>>(Bn);
    zero_sums<<<(Bn * DOUT + 255) / 256, 256>>>(Bn * DOUT);
    cvt_weights<<<64, 256>>>(W1, W2, W3);

    const int tiles = (N + MT - 1) / MT;
    mlp_mma<<<tiles, TPB, SMEM_BYTES>>>(z, b1, g1, be1, b2, g2, be2, b3, N);

    finalize_means<<<(Bn * DOUT + 255) / 256, 256>>>(Bn);

    const long long total4 = (long long)N * (DOUT / 4);
    broadcast_out<<<(int)((total4 + 255) / 256), 256>>>((float4*)d_out, total4);
}

// round 8
// speedup vs baseline: 2.4920x; 1.0177x over previous
#include <cuda_runtime.h>
#include <cuda_fp16.h>

#define TPB    256
#define MT     64          // points per tile
#define HDIM   256
#define DIN    16
#define DOUT   128
#define PITCHH 264         // sbuf pitch in halves; word-stride 132 -> conflict-free frags
#define FPITCH 132         // float view pitch for layer-3 C / epilogue
#define ZPH    24          // z tile pitch in halves
#define BMAX   4096
#define NMAX   1100000

// ---------------- device scratch (no allocations allowed) ----------------
__device__ long long d_offs[BMAX + 1];
__device__ int       d_seg[NMAX];
__device__ float     d_sums[BMAX * DOUT];
__device__ float     d_emb[BMAX * DOUT];
// fp16 k16-chunk packed weights: index (kc*N + n)*4 + tg -> uint2
//   .x = {W[16kc+2tg][n], W[16kc+2tg+1][n]}   .y = {W[16kc+8+2tg][n], W[16kc+8+2tg+1][n]}
__device__ uint2     d_W1h[1  * HDIM * 4];
__device__ uint2     d_W2h[16 * HDIM * 4];
__device__ uint2     d_W3h[16 * DOUT * 4];

// ---------------- helpers ----------------
__device__ __forceinline__ unsigned h2u(float a, float b) {
    __half2 h = __floats2half2_rn(a, b);
    return *reinterpret_cast<unsigned*>(&h);
}

__device__ __forceinline__ void mma_f16(float4& d,
                                        unsigned a0, unsigned a1, unsigned a2, unsigned a3,
                                        unsigned b0, unsigned b1) {
    asm volatile(
        "mma.sync.aligned.m16n8k16.row.col.f32.f16.f16.f32 "
        "{%0,%1,%2,%3}, {%4,%5,%6,%7}, {%8,%9}, {%0,%1,%2,%3};"
        : "+f"(d.x), "+f"(d.y), "+f"(d.z), "+f"(d.w)
        : "r"(a0), "r"(a1), "r"(a2), "r"(a3), "r"(b0), "r"(b1));
}

__device__ __forceinline__ long long get_count(const void* np, int i, int is64) {
    if (is64) return ((const long long*)np)[i];
    return (long long)((const int*)np)[i];
}

// ---------------- small setup kernels ----------------
__global__ void scan_offsets(const void* __restrict__ np, int Bn) {
    __shared__ long long part[256];
    __shared__ int s_is64;
    if (threadIdx.x == 0) {
        const int* p32 = (const int*)np;
        int is64 = 1;
        for (int i = 1; i < 7 && i < 2 * Bn; i += 2)
            if (p32[i] != 0) is64 = 0;
        s_is64 = is64;
    }
    __syncthreads();
    const int is64 = s_is64;
    const int chunk = (Bn + 255) / 256;
    const int c0 = threadIdx.x * chunk;
    long long s = 0;
    for (int i = 0; i < chunk; i++) {
        int idx = c0 + i;
        if (idx < Bn) s += get_count(np, idx, is64);
    }
    part[threadIdx.x] = s;
    __syncthreads();
    if (threadIdx.x == 0) {
        long long r = 0;
        for (int i = 0; i < 256; i++) { long long t = part[i]; part[i] = r; r += t; }
    }
    __syncthreads();
    long long base = part[threadIdx.x];
    for (int i = 0; i < chunk; i++) {
        int idx = c0 + i;
        if (idx < Bn) {
            d_offs[idx] = base;
            base += get_count(np, idx, is64);
            if (idx == Bn - 1) d_offs[Bn] = base;
        }
    }
}

__global__ void fill_seg(int Bn) {
    int b = blockIdx.x;
    long long lo = d_offs[b], hi = d_offs[b + 1];
    for (long long i = lo + threadIdx.x; i < hi; i += blockDim.x)
        d_seg[i] = b;
}

__global__ void zero_sums(int n) {
    int i = blockIdx.x * blockDim.x + threadIdx.x;
    if (i < n) d_sums[i] = 0.f;
}

// pack weights into fp16 k16-chunk layout
__global__ void cvt_weights(const float* __restrict__ W1,
                            const float* __restrict__ W2,
                            const float* __restrict__ W3) {
    int i = blockIdx.x * 256 + threadIdx.x;   // launch >= 16384 threads
    if (i < 16 * HDIM * 4) {
        int tg = i & 3, n = (i >> 2) & (HDIM - 1), kc = i >> 10;
        int k = 16 * kc + 2 * tg;
        d_W2h[i] = make_uint2(h2u(W2[k * HDIM + n],       W2[(k + 1) * HDIM + n]),
                              h2u(W2[(k + 8) * HDIM + n], W2[(k + 9) * HDIM + n]));
    }
    if (i < 16 * DOUT * 4) {
        int tg = i & 3, n = (i >> 2) & (DOUT - 1), kc = i >> 9;
        int k = 16 * kc + 2 * tg;
        d_W3h[i] = make_uint2(h2u(W3[k * DOUT + n],       W3[(k + 1) * DOUT + n]),
                              h2u(W3[(k + 8) * DOUT + n], W3[(k + 9) * DOUT + n]));
    }
    if (i < 1 * HDIM * 4) {
        int tg = i & 3, n = i >> 2;
        int k = 2 * tg;
        d_W1h[i] = make_uint2(h2u(W1[k * HDIM + n],       W1[(k + 1) * HDIM + n]),
                              h2u(W1[(k + 8) * HDIM + n], W1[(k + 9) * HDIM + n]));
    }
}

// ---------------- in-register LN + ReLU -> fp16 smem (2m x 8n warp layout) ----------------
// acc[m][t]: {x,y}=row rb+16m+g cols n0+8t+2tg{,+1}; {z,w}=row rb+16m+g+8 same cols.
__device__ __forceinline__ void ln_relu_reg(
    float4 (&acc)[2][8], __half* __restrict__ sbufh,
    const float* __restrict__ bi, const float* __restrict__ ga, const float* __restrict__ be,
    float* __restrict__ red_s, float* __restrict__ red_q,
    float* __restrict__ s_m, float* __restrict__ s_r,
    int g, int tg, int n0, int rb, int nq, int tid)
{
    #pragma unroll
    for (int t = 0; t < 8; t++) {
        const float2 bb = *(const float2*)(bi + n0 + 8 * t + 2 * tg);
        #pragma unroll
        for (int m = 0; m < 2; m++) {
            acc[m][t].x += bb.x; acc[m][t].y += bb.y;
            acc[m][t].z += bb.x; acc[m][t].w += bb.y;
        }
    }
    float s[2][2], q[2][2];
    #pragma unroll
    for (int m = 0; m < 2; m++) {
        float sl = 0.f, ql = 0.f, sh = 0.f, qh = 0.f;
        #pragma unroll
        for (int t = 0; t < 8; t++) {
            float4 v = acc[m][t];
            sl += v.x + v.y;  ql += v.x * v.x + v.y * v.y;
            sh += v.z + v.w;  qh += v.z * v.z + v.w * v.w;
        }
        s[m][0] = sl; q[m][0] = ql; s[m][1] = sh; q[m][1] = qh;
    }
    #pragma unroll
    for (int o = 1; o <= 2; o <<= 1) {
        #pragma unroll
        for (int m = 0; m < 2; m++) {
            #pragma unroll
            for (int h = 0; h < 2; h++) {
                s[m][h] += __shfl_xor_sync(0xffffffffu, s[m][h], o);
                q[m][h] += __shfl_xor_sync(0xffffffffu, q[m][h], o);
            }
        }
    }
    if (tg == 0) {
        #pragma unroll
        for (int m = 0; m < 2; m++) {
            red_s[(rb + 16 * m + g) * 4 + nq]     = s[m][0];
            red_q[(rb + 16 * m + g) * 4 + nq]     = q[m][0];
            red_s[(rb + 16 * m + g + 8) * 4 + nq] = s[m][1];
            red_q[(rb + 16 * m + g + 8) * 4 + nq] = q[m][1];
        }
    }
    __syncthreads();
    if (tid < MT) {
        float ss = 0.f, qq = 0.f;
        #pragma unroll
        for (int w = 0; w < 4; w++) { ss += red_s[tid * 4 + w]; qq += red_q[tid * 4 + w]; }
        float mm = ss * (1.f / 256.f);
        s_m[tid] = mm;
        s_r[tid] = rsqrtf(qq * (1.f / 256.f) - mm * mm + 1e-5f);
    }
    __syncthreads();
    #pragma unroll
    for (int m = 0; m < 2; m++) {
        const int rl_ = rb + 16 * m + g;
        const float ml = s_m[rl_],     rl = s_r[rl_];
        const float mh = s_m[rl_ + 8], rh = s_r[rl_ + 8];
        #pragma unroll
        for (int t = 0; t < 8; t++) {
            const int col = n0 + 8 * t + 2 * tg;
            const float2 gg = *(const float2*)(ga + col);
            const float2 ee = *(const float2*)(be + col);
            unsigned lo = h2u(fmaxf((acc[m][t].x - ml) * rl * gg.x + ee.x, 0.f),
                              fmaxf((acc[m][t].y - ml) * rl * gg.y + ee.y, 0.f));
            unsigned hi = h2u(fmaxf((acc[m][t].z - mh) * rh * gg.x + ee.x, 0.f),
                              fmaxf((acc[m][t].w - mh) * rh * gg.y + ee.y, 0.f));
            *(unsigned*)(sbufh + rl_ * PITCHH + col)       = lo;
            *(unsigned*)(sbufh + (rl_ + 8) * PITCHH + col) = hi;
        }
    }
    __syncthreads();
}

// ---------------- main fused persistent kernel ----------------
__global__ __launch_bounds__(TPB, 2)
void mlp_mma(const float* __restrict__ z,
             const float* __restrict__ b1, const float* __restrict__ g1, const float* __restrict__ be1,
             const float* __restrict__ b2, const float* __restrict__ g2, const float* __restrict__ be2,
             const float* __restrict__ b3,
             int Npts, int ntiles)
{
    extern __shared__ char smem_raw[];
    __half* sbufh = (__half*)smem_raw;              // 64*PITCHH halves
    __half* zsh   = sbufh + MT * PITCHH;            // 64*ZPH halves
    float* sb1   = (float*)(zsh + MT * ZPH);
    float* sg1   = sb1 + HDIM;
    float* sbe1  = sg1 + HDIM;
    float* sb2   = sbe1 + HDIM;
    float* sg2   = sb2 + HDIM;
    float* sbe2  = sg2 + HDIM;
    float* sb3   = sbe2 + HDIM;                     // 128
    float* red_s = sb3 + DOUT;                      // 256
    float* red_q = red_s + 256;                     // 256
    float* s_m   = red_q + 256;                     // 64
    float* s_r   = s_m + MT;                        // 64
    int*   ssg   = (int*)(s_r + MT);                // 64
    float* fbuf  = (float*)smem_raw;                // layer-3 C view, pitch FPITCH

    const int tid = threadIdx.x;
    const int warp = tid >> 5, lane = tid & 31;
    const int g = lane >> 2, tg = lane & 3;
    const int nq = warp & 3, mh = warp >> 2;
    const int rb = 32 * mh;                         // row base (32-row half)
    const int n0 = 64 * nq;                         // 64-col slice for H=256 layers
    const int n3 = 32 * nq;                         // 32-col slice for DOUT=128

    // ---- one-time param load ----
    sb1[tid] = b1[tid]; sg1[tid] = g1[tid]; sbe1[tid] = be1[tid];
    sb2[tid] = b2[tid]; sg2[tid] = g2[tid]; sbe2[tid] = be2[tid];
    if (tid < DOUT) sb3[tid] = b3[tid];
    __syncthreads();

    uint2 bw0[4], bw1[4];   // B-fragment pipeline registers
    float4 acc[2][8];

    for (int tile = blockIdx.x; tile < ntiles; tile += gridDim.x) {
        const int p0 = tile * MT;
        const int npts = min(MT, Npts - p0);

        // ---- layer-1 weights (L1-resident after first iteration) ----
        uint2 w1h[8];
        #pragma unroll
        for (int t = 0; t < 8; t++)
            w1h[t] = d_W1h[(n0 + 8 * t + g) * 4 + tg];

        // ---- z tile + seg ids ----
        {
            const float4* z4 = (const float4*)(z + (long long)p0 * DIN);
            int pi = tid >> 2, ci = tid & 3;
            float4 v = make_float4(0.f, 0.f, 0.f, 0.f);
            if (pi < npts) v = z4[pi * 4 + ci];
            *(uint2*)(zsh + pi * ZPH + 4 * ci) = make_uint2(h2u(v.x, v.y), h2u(v.z, v.w));
            if (tid < MT) ssg[tid] = (tid < npts) ? d_seg[p0 + tid] : 0;
        }
        __syncthreads();

        // ================= Layer 1: [64x16] @ [16x256], single k16 chunk =================
        #pragma unroll
        for (int m = 0; m < 2; m++)
            #pragma unroll
            for (int t = 0; t < 8; t++) acc[m][t] = make_float4(0.f, 0.f, 0.f, 0.f);

        {
            unsigned a[2][4];
            #pragma unroll
            for (int m = 0; m < 2; m++) {
                const __half* ar = zsh + (rb + 16 * m + g) * ZPH + 2 * tg;
                a[m][0] = *(const unsigned*)(ar);
                a[m][1] = *(const unsigned*)(ar + 8 * ZPH);
                a[m][2] = *(const unsigned*)(ar + 8);
                a[m][3] = *(const unsigned*)(ar + 8 * ZPH + 8);
            }
            #pragma unroll
            for (int t = 0; t < 8; t++)
                #pragma unroll
                for (int m = 0; m < 2; m++)
                    mma_f16(acc[m][t], a[m][0], a[m][1], a[m][2], a[m][3],
                            w1h[t].x, w1h[t].y);
        }
        // preload layer-2 chunk0 low half (latency hidden under LN1)
        #pragma unroll
        for (int t = 0; t < 4; t++)
            bw0[t] = d_W2h[(n0 + 8 * t + g) * 4 + tg];

        ln_relu_reg(acc, sbufh, sb1, sg1, sbe1, red_s, red_q, s_m, s_r, g, tg, n0, rb, nq, tid);

        // ================= Layer 2: [64x256] @ [256x256], 16 k16 chunks =================
        #pragma unroll
        for (int m = 0; m < 2; m++)
            #pragma unroll
            for (int t = 0; t < 8; t++) acc[m][t] = make_float4(0.f, 0.f, 0.f, 0.f);

        #pragma unroll 1
        for (int c = 0; c < 16; c++) {
            // prefetch high half of chunk c
            #pragma unroll
            for (int t = 0; t < 4; t++)
                bw1[t] = d_W2h[(c * HDIM + n0 + 32 + 8 * t + g) * 4 + tg];
            const int k = 16 * c;
            unsigned a[2][4];
            #pragma unroll
            for (int m = 0; m < 2; m++) {
                const __half* ar = sbufh + (rb + 16 * m + g) * PITCHH + k + 2 * tg;
                a[m][0] = *(const unsigned*)(ar);
                a[m][1] = *(const unsigned*)(ar + 8 * PITCHH);
                a[m][2] = *(const unsigned*)(ar + 8);
                a[m][3] = *(const unsigned*)(ar + 8 * PITCHH + 8);
            }
            // compute low half (t=0..3) with bw0
            #pragma unroll
            for (int t = 0; t < 4; t++)
                #pragma unroll
                for (int m = 0; m < 2; m++)
                    mma_f16(acc[m][t], a[m][0], a[m][1], a[m][2], a[m][3],
                            bw0[t].x, bw0[t].y);
            // prefetch low half of chunk c+1
            if (c + 1 < 16) {
                #pragma unroll
                for (int t = 0; t < 4; t++)
                    bw0[t] = d_W2h[((c + 1) * HDIM + n0 + 8 * t + g) * 4 + tg];
            }
            // compute high half (t=4..7) with bw1
            #pragma unroll
            for (int t = 0; t < 4; t++)
                #pragma unroll
                for (int m = 0; m < 2; m++)
                    mma_f16(acc[m][4 + t], a[m][0], a[m][1], a[m][2], a[m][3],
                            bw1[t].x, bw1[t].y);
        }
        // preload layer-3 chunk0 (hidden under LN2)
        #pragma unroll
        for (int t = 0; t < 4; t++)
            bw0[t] = d_W3h[(n3 + 8 * t + g) * 4 + tg];

        ln_relu_reg(acc, sbufh, sb2, sg2, sbe2, red_s, red_q, s_m, s_r, g, tg, n0, rb, nq, tid);

        // ================= Layer 3: [64x256] @ [256x128] =================
        {
            float4 acc3[2][4];
            #pragma unroll
            for (int m = 0; m < 2; m++)
                #pragma unroll
                for (int t = 0; t < 4; t++) acc3[m][t] = make_float4(0.f, 0.f, 0.f, 0.f);

            #pragma unroll 1
            for (int c = 0; c < 16; c += 2) {
                #pragma unroll
                for (int t = 0; t < 4; t++)
                    bw1[t] = d_W3h[((c + 1) * DOUT + n3 + 8 * t + g) * 4 + tg];
                {
                    const int k = 16 * c;
                    unsigned a[2][4];
                    #pragma unroll
                    for (int m = 0; m < 2; m++) {
                        const __half* ar = sbufh + (rb + 16 * m + g) * PITCHH + k + 2 * tg;
                        a[m][0] = *(const unsigned*)(ar);
                        a[m][1] = *(const unsigned*)(ar + 8 * PITCHH);
                        a[m][2] = *(const unsigned*)(ar + 8);
                        a[m][3] = *(const unsigned*)(ar + 8 * PITCHH + 8);
                    }
                    #pragma unroll
                    for (int t = 0; t < 4; t++)
                        #pragma unroll
                        for (int m = 0; m < 2; m++)
                            mma_f16(acc3[m][t], a[m][0], a[m][1], a[m][2], a[m][3],
                                    bw0[t].x, bw0[t].y);
                }
                if (c + 2 < 16) {
                    #pragma unroll
                    for (int t = 0; t < 4; t++)
                        bw0[t] = d_W3h[((c + 2) * DOUT + n3 + 8 * t + g) * 4 + tg];
                }
                {
                    const int k = 16 * (c + 1);
                    unsigned a[2][4];
                    #pragma unroll
                    for (int m = 0; m < 2; m++) {
                        const __half* ar = sbufh + (rb + 16 * m + g) * PITCHH + k + 2 * tg;
                        a[m][0] = *(const unsigned*)(ar);
                        a[m][1] = *(const unsigned*)(ar + 8 * PITCHH);
                        a[m][2] = *(const unsigned*)(ar + 8);
                        a[m][3] = *(const unsigned*)(ar + 8 * PITCHH + 8);
                    }
                    #pragma unroll
                    for (int t = 0; t < 4; t++)
                        #pragma unroll
                        for (int m = 0; m < 2; m++)
                            mma_f16(acc3[m][t], a[m][0], a[m][1], a[m][2], a[m][3],
                                    bw1[t].x, bw1[t].y);
                }
            }
            __syncthreads();   // all sbuf A reads done before overwriting with C3 (float view)
            #pragma unroll
            for (int m = 0; m < 2; m++)
                #pragma unroll
                for (int t = 0; t < 4; t++) {
                    float* cr = fbuf + (rb + 16 * m + g) * FPITCH + n3 + 8 * t + 2 * tg;
                    cr[0] = acc3[m][t].x; cr[1] = acc3[m][t].y;
                    cr[8 * FPITCH] = acc3[m][t].z; cr[8 * FPITCH + 1] = acc3[m][t].w;
                }
        }
        __syncthreads();

        // ================= epilogue: bias + run-length segment accumulate =================
        {
            const int f = tid & (DOUT - 1);
            const int half = tid >> 7;
            const int ps = half * 32;
            const int pe = min(ps + 32, npts);
            if (ps < pe) {
                const float bf = sb3[f];
                int cur = ssg[ps];
                float run = 0.f;
                for (int p = ps; p < pe; p++) {
                    float phi = fbuf[p * FPITCH + f] + bf;
                    int sp = ssg[p];
                    if (sp != cur) {
                        atomicAdd(&d_sums[cur * DOUT + f], run);
                        run = 0.f;
                        cur = sp;
                    }
                    run += phi;
                }
                atomicAdd(&d_sums[cur * DOUT + f], run);
            }
        }
        __syncthreads();   // fbuf/ssg reads done before next iteration overwrites
    }
}

__global__ void finalize_means(int Bn) {
    int i = blockIdx.x * blockDim.x + threadIdx.x;
    if (i < Bn * DOUT) {
        int b = i >> 7;
        float cnt = (float)(d_offs[b + 1] - d_offs[b]);
        d_emb[i] = d_sums[i] / cnt;
    }
}

__global__ void broadcast_out(float4* __restrict__ out, long long total4) {
    long long i = (long long)blockIdx.x * blockDim.x + threadIdx.x;
    if (i < total4) {
        long long p = i >> 5;
        int c = (int)(i & 31);
        const float4* emb4 = reinterpret_cast<const float4*>(d_emb);
        out[i] = emb4[(long long)d_seg[p] * 32 + c];
    }
}

extern "C" void kernel_launch(void* const* d_in, const int* in_sizes, int n_in,
                              void* d_out, int out_size) {
    const float* z   = (const float*)d_in[0];
    const float* W1  = (const float*)d_in[1];
    const float* b1  = (const float*)d_in[2];
    const float* g1  = (const float*)d_in[3];
    const float* be1 = (const float*)d_in[4];
    const float* W2  = (const float*)d_in[5];
    const float* b2  = (const float*)d_in[6];
    const float* g2  = (const float*)d_in[7];
    const float* be2 = (const float*)d_in[8];
    const float* W3  = (const float*)d_in[9];
    const float* b3  = (const float*)d_in[10];
    const void*  np  = d_in[11];

    const int Bn = in_sizes[11];
    const int N  = in_sizes[0] / DIN;

    static const size_t SMEM_BYTES =
        (MT * PITCHH + MT * ZPH) * sizeof(__half)
        + (6 * HDIM + DOUT + 256 + 256 + 2 * MT) * sizeof(float)
        + MT * sizeof(int);
    cudaFuncSetAttribute(mlp_mma, cudaFuncAttributeMaxDynamicSharedMemorySize,
                         (int)SMEM_BYTES);

    int dev = 0, nsm = 148;
    cudaGetDevice(&dev);
    cudaDeviceGetAttribute(&nsm, cudaDevAttrMultiProcessorCount, dev);

    scan_offsets<<<1, 256>>>(np, Bn);
    fill_seg<<<Bn, 128>>>(Bn);
    zero_sums<<<(Bn * DOUT + 255) / 256, 256>>>(Bn * DOUT);
    cvt_weights<<<64, 256>>>(W1, W2, W3);

    const int ntiles = (N + MT - 1) / MT;
    int grid = 2 * nsm;
    if (grid > ntiles) grid = ntiles;
    mlp_mma<<<grid, TPB, SMEM_BYTES>>>(z, b1, g1, be1, b2, g2, be2, b3, N, ntiles);

    finalize_means<<<(Bn * DOUT + 255) / 256, 256>>>(Bn);

    const long long total4 = (long long)N * (DOUT / 4);
    broadcast_out<<<(int)((total4 + 255) / 256), 256>>>((float4*)d_out, total4);
}

// round 9
// speedup vs baseline: 2.4965x; 1.0018x over previous
#include <cuda_runtime.h>
#include <cuda_fp16.h>

#define TPB    256
#define MT     64          // points per tile
#define HDIM   256
#define DIN    16
#define DOUT   128
#define PITCHH 264         // sbuf pitch in halves; row stride 528B -> LDSM conflict-free
#define FPITCH 132         // float view pitch for layer-3 C / epilogue
#define ZPH    24          // z tile pitch in halves
#define BMAX   4096
#define NMAX   1100000

// ---------------- device scratch (no allocations allowed) ----------------
__device__ long long d_offs[BMAX + 1];
__device__ int       d_seg[NMAX];
__device__ float     d_sums[BMAX * DOUT];
__device__ float     d_emb[BMAX * DOUT];
// fp16 k16-chunk packed weights: index (kc*N + n)*4 + tg -> uint2
__device__ uint2     d_W1h[1  * HDIM * 4];
__device__ uint2     d_W2h[16 * HDIM * 4];
__device__ uint2     d_W3h[16 * DOUT * 4];

// ---------------- helpers ----------------
__device__ __forceinline__ unsigned h2u(float a, float b) {
    __half2 h = __floats2half2_rn(a, b);
    return *reinterpret_cast<unsigned*>(&h);
}

__device__ __forceinline__ void mma_f16(float4& d,
                                        unsigned a0, unsigned a1, unsigned a2, unsigned a3,
                                        unsigned b0, unsigned b1) {
    asm volatile(
        "mma.sync.aligned.m16n8k16.row.col.f32.f16.f16.f32 "
        "{%0,%1,%2,%3}, {%4,%5,%6,%7}, {%8,%9}, {%0,%1,%2,%3};"
        : "+f"(d.x), "+f"(d.y), "+f"(d.z), "+f"(d.w)
        : "r"(a0), "r"(a1), "r"(a2), "r"(a3), "r"(b0), "r"(b1));
}

__device__ __forceinline__ void ldsm_x4(unsigned& r0, unsigned& r1, unsigned& r2, unsigned& r3,
                                        unsigned addr) {
    asm volatile("ldmatrix.sync.aligned.m8n8.x4.shared.b16 {%0,%1,%2,%3}, [%4];"
                 : "=r"(r0), "=r"(r1), "=r"(r2), "=r"(r3) : "r"(addr));
}

__device__ __forceinline__ unsigned smem_u32(const void* p) {
    return (unsigned)__cvta_generic_to_shared(p);
}

__device__ __forceinline__ long long get_count(const void* np, int i, int is64) {
    if (is64) return ((const long long*)np)[i];
    return (long long)((const int*)np)[i];
}

// ---------------- small setup kernels ----------------
__global__ void scan_offsets(const void* __restrict__ np, int Bn) {
    __shared__ long long part[256];
    __shared__ int s_is64;
    if (threadIdx.x == 0) {
        const int* p32 = (const int*)np;
        int is64 = 1;
        for (int i = 1; i < 7 && i < 2 * Bn; i += 2)
            if (p32[i] != 0) is64 = 0;
        s_is64 = is64;
    }
    __syncthreads();
    const int is64 = s_is64;
    const int chunk = (Bn + 255) / 256;
    const int c0 = threadIdx.x * chunk;
    long long s = 0;
    for (int i = 0; i < chunk; i++) {
        int idx = c0 + i;
        if (idx < Bn) s += get_count(np, idx, is64);
    }
    part[threadIdx.x] = s;
    __syncthreads();
    if (threadIdx.x == 0) {
        long long r = 0;
        for (int i = 0; i < 256; i++) { long long t = part[i]; part[i] = r; r += t; }
    }
    __syncthreads();
    long long base = part[threadIdx.x];
    for (int i = 0; i < chunk; i++) {
        int idx = c0 + i;
        if (idx < Bn) {
            d_offs[idx] = base;
            base += get_count(np, idx, is64);
            if (idx == Bn - 1) d_offs[Bn] = base;
        }
    }
}

// fused: blocks [0,Bn) fill seg ids; blocks [Bn, ...) zero d_sums
__global__ void fill_seg_zero(int Bn) {
    int b = blockIdx.x;
    if (b < Bn) {
        long long lo = d_offs[b], hi = d_offs[b + 1];
        for (long long i = lo + threadIdx.x; i < hi; i += blockDim.x)
            d_seg[i] = b;
    } else {
        int i = (b - Bn) * blockDim.x + threadIdx.x;
        if (i < Bn * DOUT) d_sums[i] = 0.f;
    }
}

// pack weights into fp16 k16-chunk layout
__global__ void cvt_weights(const float* __restrict__ W1,
                            const float* __restrict__ W2,
                            const float* __restrict__ W3) {
    int i = blockIdx.x * 256 + threadIdx.x;
    if (i < 16 * HDIM * 4) {
        int tg = i & 3, n = (i >> 2) & (HDIM - 1), kc = i >> 10;
        int k = 16 * kc + 2 * tg;
        d_W2h[i] = make_uint2(h2u(W2[k * HDIM + n],       W2[(k + 1) * HDIM + n]),
                              h2u(W2[(k + 8) * HDIM + n], W2[(k + 9) * HDIM + n]));
    }
    if (i < 16 * DOUT * 4) {
        int tg = i & 3, n = (i >> 2) & (DOUT - 1), kc = i >> 9;
        int k = 16 * kc + 2 * tg;
        d_W3h[i] = make_uint2(h2u(W3[k * DOUT + n],       W3[(k + 1) * DOUT + n]),
                              h2u(W3[(k + 8) * DOUT + n], W3[(k + 9) * DOUT + n]));
    }
    if (i < 1 * HDIM * 4) {
        int tg = i & 3, n = i >> 2;
        int k = 2 * tg;
        d_W1h[i] = make_uint2(h2u(W1[k * HDIM + n],       W1[(k + 1) * HDIM + n]),
                              h2u(W1[(k + 8) * HDIM + n], W1[(k + 9) * HDIM + n]));
    }
}

// ---------------- in-register LN + ReLU -> fp16 smem (2m x 8n warp layout) ----------------
__device__ __forceinline__ void ln_relu_reg(
    float4 (&acc)[2][8], __half* __restrict__ sbufh,
    const float* __restrict__ bi, const float* __restrict__ ga, const float* __restrict__ be,
    float* __restrict__ red_s, float* __restrict__ red_q,
    float* __restrict__ s_m, float* __restrict__ s_r,
    int g, int tg, int n0, int rb, int nq, int tid)
{
    #pragma unroll
    for (int t = 0; t < 8; t++) {
        const float2 bb = *(const float2*)(bi + n0 + 8 * t + 2 * tg);
        #pragma unroll
        for (int m = 0; m < 2; m++) {
            acc[m][t].x += bb.x; acc[m][t].y += bb.y;
            acc[m][t].z += bb.x; acc[m][t].w += bb.y;
        }
    }
    float s[2][2], q[2][2];
    #pragma unroll
    for (int m = 0; m < 2; m++) {
        float sl = 0.f, ql = 0.f, sh = 0.f, qh = 0.f;
        #pragma unroll
        for (int t = 0; t < 8; t++) {
            float4 v = acc[m][t];
            sl += v.x + v.y;  ql += v.x * v.x + v.y * v.y;
            sh += v.z + v.w;  qh += v.z * v.z + v.w * v.w;
        }
        s[m][0] = sl; q[m][0] = ql; s[m][1] = sh; q[m][1] = qh;
    }
    #pragma unroll
    for (int o = 1; o <= 2; o <<= 1) {
        #pragma unroll
        for (int m = 0; m < 2; m++) {
            #pragma unroll
            for (int h = 0; h < 2; h++) {
                s[m][h] += __shfl_xor_sync(0xffffffffu, s[m][h], o);
                q[m][h] += __shfl_xor_sync(0xffffffffu, q[m][h], o);
            }
        }
    }
    if (tg == 0) {
        #pragma unroll
        for (int m = 0; m < 2; m++) {
            red_s[(rb + 16 * m + g) * 4 + nq]     = s[m][0];
            red_q[(rb + 16 * m + g) * 4 + nq]     = q[m][0];
            red_s[(rb + 16 * m + g + 8) * 4 + nq] = s[m][1];
            red_q[(rb + 16 * m + g + 8) * 4 + nq] = q[m][1];
        }
    }
    __syncthreads();
    if (tid < MT) {
        float ss = 0.f, qq = 0.f;
        #pragma unroll
        for (int w = 0; w < 4; w++) { ss += red_s[tid * 4 + w]; qq += red_q[tid * 4 + w]; }
        float mm = ss * (1.f / 256.f);
        s_m[tid] = mm;
        s_r[tid] = rsqrtf(qq * (1.f / 256.f) - mm * mm + 1e-5f);
    }
    __syncthreads();
    #pragma unroll
    for (int m = 0; m < 2; m++) {
        const int rl_ = rb + 16 * m + g;
        const float ml = s_m[rl_],     rl = s_r[rl_];
        const float mh = s_m[rl_ + 8], rh = s_r[rl_ + 8];
        #pragma unroll
        for (int t = 0; t < 8; t++) {
            const int col = n0 + 8 * t + 2 * tg;
            const float2 gg = *(const float2*)(ga + col);
            const float2 ee = *(const float2*)(be + col);
            unsigned lo = h2u(fmaxf((acc[m][t].x - ml) * rl * gg.x + ee.x, 0.f),
                              fmaxf((acc[m][t].y - ml) * rl * gg.y + ee.y, 0.f));
            unsigned hi = h2u(fmaxf((acc[m][t].z - mh) * rh * gg.x + ee.x, 0.f),
                              fmaxf((acc[m][t].w - mh) * rh * gg.y + ee.y, 0.f));
            *(unsigned*)(sbufh + rl_ * PITCHH + col)       = lo;
            *(unsigned*)(sbufh + (rl_ + 8) * PITCHH + col) = hi;
        }
    }
    __syncthreads();
}

// ---------------- main fused persistent kernel ----------------
__global__ __launch_bounds__(TPB, 2)
void mlp_mma(const float* __restrict__ z,
             const float* __restrict__ b1, const float* __restrict__ g1, const float* __restrict__ be1,
             const float* __restrict__ b2, const float* __restrict__ g2, const float* __restrict__ be2,
             const float* __restrict__ b3,
             int Npts, int ntiles)
{
    extern __shared__ char smem_raw[];
    __half* sbufh = (__half*)smem_raw;              // 64*PITCHH halves
    __half* zsh   = sbufh + MT * PITCHH;            // 64*ZPH halves
    float* sb1   = (float*)(zsh + MT * ZPH);
    float* sg1   = sb1 + HDIM;
    float* sbe1  = sg1 + HDIM;
    float* sb2   = sbe1 + HDIM;
    float* sg2   = sb2 + HDIM;
    float* sbe2  = sg2 + HDIM;
    float* sb3   = sbe2 + HDIM;                     // 128
    float* red_s = sb3 + DOUT;                      // 256
    float* red_q = red_s + 256;                     // 256
    float* s_m   = red_q + 256;                     // 64
    float* s_r   = s_m + MT;                        // 64
    int*   ssg   = (int*)(s_r + MT);                // 64
    float* fbuf  = (float*)smem_raw;                // layer-3 C view, pitch FPITCH

    const int tid = threadIdx.x;
    const int warp = tid >> 5, lane = tid & 31;
    const int g = lane >> 2, tg = lane & 3;
    const int nq = warp & 3, mh = warp >> 2;
    const int rb = 32 * mh;                         // row base (32-row half)
    const int n0 = 64 * nq;                         // 64-col slice for H=256 layers
    const int n3 = 32 * nq;                         // 32-col slice for DOUT=128

    // ldmatrix per-lane row/col within a 16-row A tile
    const int lrow = (lane & 7) + ((lane >> 3) & 1) * 8;   // 0..15
    const int lcol = (lane >> 4) * 8;                       // 0 or 8 (halves)
    // base LDSM addresses for the two m-tiles in sbufh (k added at use site)
    const unsigned sb_base = smem_u32(sbufh);
    unsigned lds_a0 = sb_base + (unsigned)(((rb + lrow) * PITCHH + lcol) * 2);
    unsigned lds_a1 = sb_base + (unsigned)(((rb + 16 + lrow) * PITCHH + lcol) * 2);
    // and in the z tile
    const unsigned zs_base = smem_u32(zsh);
    unsigned lds_z0 = zs_base + (unsigned)(((rb + lrow) * ZPH + lcol) * 2);
    unsigned lds_z1 = zs_base + (unsigned)(((rb + 16 + lrow) * ZPH + lcol) * 2);

    // ---- one-time param load ----
    sb1[tid] = b1[tid]; sg1[tid] = g1[tid]; sbe1[tid] = be1[tid];
    sb2[tid] = b2[tid]; sg2[tid] = g2[tid]; sbe2[tid] = be2[tid];
    if (tid < DOUT) sb3[tid] = b3[tid];
    __syncthreads();

    uint2 bw0[4], bw1[4];   // B-fragment pipeline registers
    float4 acc[2][8];

    for (int tile = blockIdx.x; tile < ntiles; tile += gridDim.x) {
        const int p0 = tile * MT;
        const int npts = min(MT, Npts - p0);

        uint2 w1h[8];
        #pragma unroll
        for (int t = 0; t < 8; t++)
            w1h[t] = d_W1h[(n0 + 8 * t + g) * 4 + tg];

        // ---- z tile + seg ids ----
        {
            const float4* z4 = (const float4*)(z + (long long)p0 * DIN);
            int pi = tid >> 2, ci = tid & 3;
            float4 v = make_float4(0.f, 0.f, 0.f, 0.f);
            if (pi < npts) v = z4[pi * 4 + ci];
            *(uint2*)(zsh + pi * ZPH + 4 * ci) = make_uint2(h2u(v.x, v.y), h2u(v.z, v.w));
            if (tid < MT) ssg[tid] = (tid < npts) ? d_seg[p0 + tid] : 0;
        }
        __syncthreads();

        // ================= Layer 1: [64x16] @ [16x256] =================
        #pragma unroll
        for (int m = 0; m < 2; m++)
            #pragma unroll
            for (int t = 0; t < 8; t++) acc[m][t] = make_float4(0.f, 0.f, 0.f, 0.f);

        {
            unsigned a[2][4];
            ldsm_x4(a[0][0], a[0][1], a[0][2], a[0][3], lds_z0);
            ldsm_x4(a[1][0], a[1][1], a[1][2], a[1][3], lds_z1);
            #pragma unroll
            for (int t = 0; t < 8; t++)
                #pragma unroll
                for (int m = 0; m < 2; m++)
                    mma_f16(acc[m][t], a[m][0], a[m][1], a[m][2], a[m][3],
                            w1h[t].x, w1h[t].y);
        }
        #pragma unroll
        for (int t = 0; t < 4; t++)
            bw0[t] = d_W2h[(n0 + 8 * t + g) * 4 + tg];

        ln_relu_reg(acc, sbufh, sb1, sg1, sbe1, red_s, red_q, s_m, s_r, g, tg, n0, rb, nq, tid);

        // ================= Layer 2: [64x256] @ [256x256], 16 k16 chunks =================
        #pragma unroll
        for (int m = 0; m < 2; m++)
            #pragma unroll
            for (int t = 0; t < 8; t++) acc[m][t] = make_float4(0.f, 0.f, 0.f, 0.f);

        #pragma unroll 1
        for (int c = 0; c < 16; c++) {
            #pragma unroll
            for (int t = 0; t < 4; t++)
                bw1[t] = d_W2h[(c * HDIM + n0 + 32 + 8 * t + g) * 4 + tg];
            const unsigned koff = (unsigned)(32 * c);   // 16 halves * 2 bytes
            unsigned a[2][4];
            ldsm_x4(a[0][0], a[0][1], a[0][2], a[0][3], lds_a0 + koff);
            ldsm_x4(a[1][0], a[1][1], a[1][2], a[1][3], lds_a1 + koff);
            #pragma unroll
            for (int t = 0; t < 4; t++)
                #pragma unroll
                for (int m = 0; m < 2; m++)
                    mma_f16(acc[m][t], a[m][0], a[m][1], a[m][2], a[m][3],
                            bw0[t].x, bw0[t].y);
            if (c + 1 < 16) {
                #pragma unroll
                for (int t = 0; t < 4; t++)
                    bw0[t] = d_W2h[((c + 1) * HDIM + n0 + 8 * t + g) * 4 + tg];
            }
            #pragma unroll
            for (int t = 0; t < 4; t++)
                #pragma unroll
                for (int m = 0; m < 2; m++)
                    mma_f16(acc[m][4 + t], a[m][0], a[m][1], a[m][2], a[m][3],
                            bw1[t].x, bw1[t].y);
        }
        #pragma unroll
        for (int t = 0; t < 4; t++)
            bw0[t] = d_W3h[(n3 + 8 * t + g) * 4 + tg];

        ln_relu_reg(acc, sbufh, sb2, sg2, sbe2, red_s, red_q, s_m, s_r, g, tg, n0, rb, nq, tid);

        // ================= Layer 3: [64x256] @ [256x128] =================
        {
            float4 acc3[2][4];
            #pragma unroll
            for (int m = 0; m < 2; m++)
                #pragma unroll
                for (int t = 0; t < 4; t++) acc3[m][t] = make_float4(0.f, 0.f, 0.f, 0.f);

            #pragma unroll 1
            for (int c = 0; c < 16; c += 2) {
                #pragma unroll
                for (int t = 0; t < 4; t++)
                    bw1[t] = d_W3h[((c + 1) * DOUT + n3 + 8 * t + g) * 4 + tg];
                {
                    const unsigned koff = (unsigned)(32 * c);
                    unsigned a[2][4];
                    ldsm_x4(a[0][0], a[0][1], a[0][2], a[0][3], lds_a0 + koff);
                    ldsm_x4(a[1][0], a[1][1], a[1][2], a[1][3], lds_a1 + koff);
                    #pragma unroll
                    for (int t = 0; t < 4; t++)
                        #pragma unroll
                        for (int m = 0; m < 2; m++)
                            mma_f16(acc3[m][t], a[m][0], a[m][1], a[m][2], a[m][3],
                                    bw0[t].x, bw0[t].y);
                }
                if (c + 2 < 16) {
                    #pragma unroll
                    for (int t = 0; t < 4; t++)
                        bw0[t] = d_W3h[((c + 2) * DOUT + n3 + 8 * t + g) * 4 + tg];
                }
                {
                    const unsigned koff = (unsigned)(32 * (c + 1));
                    unsigned a[2][4];
                    ldsm_x4(a[0][0], a[0][1], a[0][2], a[0][3], lds_a0 + koff);
                    ldsm_x4(a[1][0], a[1][1], a[1][2], a[1][3], lds_a1 + koff);
                    #pragma unroll
                    for (int t = 0; t < 4; t++)
                        #pragma unroll
                        for (int m = 0; m < 2; m++)
                            mma_f16(acc3[m][t], a[m][0], a[m][1], a[m][2], a[m][3],
                                    bw1[t].x, bw1[t].y);
                }
            }
            __syncthreads();
            #pragma unroll
            for (int m = 0; m < 2; m++)
                #pragma unroll
                for (int t = 0; t < 4; t++) {
                    float* cr = fbuf + (rb + 16 * m + g) * FPITCH + n3 + 8 * t + 2 * tg;
                    cr[0] = acc3[m][t].x; cr[1] = acc3[m][t].y;
                    cr[8 * FPITCH] = acc3[m][t].z; cr[8 * FPITCH + 1] = acc3[m][t].w;
                }
        }
        __syncthreads();

        // ================= epilogue: bias + run-length segment accumulate =================
        {
            const int f = tid & (DOUT - 1);
            const int half = tid >> 7;
            const int ps = half * 32;
            const int pe = min(ps + 32, npts);
            if (ps < pe) {
                const float bf = sb3[f];
                int cur = ssg[ps];
                float run = 0.f;
                for (int p = ps; p < pe; p++) {
                    float phi = fbuf[p * FPITCH + f] + bf;
                    int sp = ssg[p];
                    if (sp != cur) {
                        atomicAdd(&d_sums[cur * DOUT + f], run);
                        run = 0.f;
                        cur = sp;
                    }
                    run += phi;
                }
                atomicAdd(&d_sums[cur * DOUT + f], run);
            }
        }
        __syncthreads();
    }
}

__global__ void finalize_means(int Bn) {
    int i = blockIdx.x * blockDim.x + threadIdx.x;
    if (i < Bn * DOUT) {
        int b = i >> 7;
        float cnt = (float)(d_offs[b + 1] - d_offs[b]);
        d_emb[i] = d_sums[i] / cnt;
    }
}

__global__ void broadcast_out(float4* __restrict__ out, long long total4) {
    long long i = (long long)blockIdx.x * blockDim.x + threadIdx.x;
    if (i < total4) {
        long long p = i >> 5;
        int c = (int)(i & 31);
        const float4* emb4 = reinterpret_cast<const float4*>(d_emb);
        out[i] = emb4[(long long)d_seg[p] * 32 + c];
    }
}

extern "C" void kernel_launch(void* const* d_in, const int* in_sizes, int n_in,
                              void* d_out, int out_size) {
    const float* z   = (const float*)d_in[0];
    const float* W1  = (const float*)d_in[1];
    const float* b1  = (const float*)d_in[2];
    const float* g1  = (const float*)d_in[3];
    const float* be1 = (const float*)d_in[4];
    const float* W2  = (const float*)d_in[5];
    const float* b2  = (const float*)d_in[6];
    const float* g2  = (const float*)d_in[7];
    const float* be2 = (const float*)d_in[8];
    const float* W3  = (const float*)d_in[9];
    const float* b3  = (const float*)d_in[10];
    const void*  np  = d_in[11];

    const int Bn = in_sizes[11];
    const int N  = in_sizes[0] / DIN;

    static const size_t SMEM_BYTES =
        (MT * PITCHH + MT * ZPH) * sizeof(__half)
        + (6 * HDIM + DOUT + 256 + 256 + 2 * MT) * sizeof(float)
        + MT * sizeof(int);
    cudaFuncSetAttribute(mlp_mma, cudaFuncAttributeMaxDynamicSharedMemorySize,
                         (int)SMEM_BYTES);

    int dev = 0, nsm = 148;
    cudaGetDevice(&dev);
    cudaDeviceGetAttribute(&nsm, cudaDevAttrMultiProcessorCount, dev);

    // Launch order arranged so mlp_mma is the 4th launch (ncu capture slot).
    scan_offsets<<<1, 256>>>(np, Bn);
    cvt_weights<<<64, 256>>>(W1, W2, W3);
    fill_seg_zero<<<Bn + (Bn * DOUT + 127) / 128, 128>>>(Bn);

    const int ntiles = (N + MT - 1) / MT;
    int grid = 2 * nsm;
    if (grid > ntiles) grid = ntiles;
    mlp_mma<<<grid, TPB, SMEM_BYTES>>>(z, b1, g1, be1, b2, g2, be2, b3, N, ntiles);

    finalize_means<<<(Bn * DOUT + 255) / 256, 256>>>(Bn);

    const long long total4 = (long long)N * (DOUT / 4);
    broadcast_out<<<(int)((total4 + 255) / 256), 256>>>((float4*)d_out, total4);
}